// round 1
// baseline (speedup 1.0000x reference)
#include <cuda_runtime.h>

#define B_  8
#define T_  2048
#define DM  1024
#define DH  64
#define BT  (B_*T_)

// Scratch for projected Q, K, V: [B*T, 64] each (12 MB total, static device mem)
__device__ float g_Q[BT * DH];
__device__ float g_K[BT * DH];
__device__ float g_V[BT * DH];

// ---------------------------------------------------------------------------
// Kernel 1: fused QKV projection.
// Grid: BT/64 = 256 blocks, 256 threads.
// Each block computes a [64 x 192] output tile (192 = 64 Q | 64 K | 64 V cols).
// Thread tile: 4 rows x 12 cols.
// ---------------------------------------------------------------------------
__global__ __launch_bounds__(256) void proj_kernel(
    const float* __restrict__ x,
    const float* __restrict__ Wq,
    const float* __restrict__ Wk,
    const float* __restrict__ Wv)
{
    __shared__ float xs[64][33];    // [row][k] padded (33) to kill bank conflicts
    __shared__ float ws[32][192];   // [k][col]  (float4-aligned rows)

    const int tid = threadIdx.x;
    const int tx  = tid & 15;       // col group: cols tx*12 .. tx*12+11
    const int ty  = tid >> 4;       // row group: rows ty*4  .. ty*4+3
    const int row0 = blockIdx.x * 64;

    float acc[4][12];
    #pragma unroll
    for (int i = 0; i < 4; i++)
        #pragma unroll
        for (int j = 0; j < 12; j++) acc[i][j] = 0.0f;

    for (int kk0 = 0; kk0 < DM; kk0 += 32) {
        // --- load x tile [64 x 32] (512 float4, 2 per thread) ---
        #pragma unroll
        for (int l = 0; l < 2; l++) {
            int lin = tid + l * 256;          // 0..511
            int r   = lin >> 3;               // 0..63
            int c4  = lin & 7;                // 0..7
            float4 v = ((const float4*)x)[(size_t)(row0 + r) * (DM/4) + (kk0 >> 2) + c4];
            xs[r][c4*4 + 0] = v.x;
            xs[r][c4*4 + 1] = v.y;
            xs[r][c4*4 + 2] = v.z;
            xs[r][c4*4 + 3] = v.w;
        }
        // --- load W tile [32 x 192] (1536 float4, 6 per thread) ---
        #pragma unroll
        for (int l = 0; l < 6; l++) {
            int lin = tid + l * 256;          // 0..1535
            int r   = lin / 48;               // 0..31
            int c4  = lin % 48;               // 0..47
            int mat = c4 >> 4;                // 0:Q 1:K 2:V
            int cc  = c4 & 15;                // 0..15
            const float* Wp = (mat == 0) ? Wq : (mat == 1) ? Wk : Wv;
            float4 v = ((const float4*)Wp)[(size_t)(kk0 + r) * (DH/4) + cc];
            *(float4*)&ws[r][c4 * 4] = v;
        }
        __syncthreads();

        #pragma unroll
        for (int k = 0; k < 32; k++) {
            float xr[4];
            #pragma unroll
            for (int i = 0; i < 4; i++) xr[i] = xs[ty*4 + i][k];
            float wr[12];
            #pragma unroll
            for (int j4 = 0; j4 < 3; j4++) {
                float4 v = *(const float4*)&ws[k][tx*12 + j4*4];
                wr[j4*4+0] = v.x; wr[j4*4+1] = v.y; wr[j4*4+2] = v.z; wr[j4*4+3] = v.w;
            }
            #pragma unroll
            for (int i = 0; i < 4; i++)
                #pragma unroll
                for (int j = 0; j < 12; j++)
                    acc[i][j] = fmaf(xr[i], wr[j], acc[i][j]);
        }
        __syncthreads();
    }

    // --- scatter to Q/K/V scratch ---
    #pragma unroll
    for (int i = 0; i < 4; i++) {
        size_t row = (size_t)(row0 + ty*4 + i);
        #pragma unroll
        for (int j = 0; j < 12; j++) {
            int c = tx*12 + j;
            float v = acc[i][j];
            if (c < 64)       g_Q[row * DH + c]       = v;
            else if (c < 128) g_K[row * DH + (c-64)]  = v;
            else              g_V[row * DH + (c-128)] = v;
        }
    }
}

// ---------------------------------------------------------------------------
// Kernel 2: causal flash attention, fp32.
// Grid: (T/64, B) = (32, 8); 128 threads.
// Thread tile: 4 q-rows (ty=0..15) x 8 cols (tx=0..7); col c = j*8 + tx.
// Smem: Qs | KV (K then V reuse) | Ps, each [64][PAD].
// ---------------------------------------------------------------------------
#define PAD 68
#define ATTN_SMEM_BYTES (3 * 64 * PAD * (int)sizeof(float))

__global__ __launch_bounds__(128) void attn_kernel(float* __restrict__ out)
{
    extern __shared__ float sm[];
    float* Qs = sm;
    float* KV = sm + 64 * PAD;
    float* Ps = sm + 2 * 64 * PAD;

    const int tid = threadIdx.x;
    const int tx  = tid & 7;
    const int ty  = tid >> 3;
    const int qt  = gridDim.x - 1 - blockIdx.x;   // long rows first
    const int b   = blockIdx.y;
    const int q0  = qt * 64;

    // --- load Q tile, pre-scaled by 1/sqrt(64) = 0.125 ---
    {
        const float* Qg = g_Q + ((size_t)b * T_ + q0) * DH;
        #pragma unroll
        for (int l = 0; l < 8; l++) {
            int lin = tid + l * 128;      // 0..1023
            int r = lin >> 4, c4 = lin & 15;
            float4 v = ((const float4*)Qg)[r * 16 + c4];
            v.x *= 0.125f; v.y *= 0.125f; v.z *= 0.125f; v.w *= 0.125f;
            *(float4*)&Qs[r * PAD + c4 * 4] = v;
        }
    }

    float m[4], l[4], acc[4][8];
    #pragma unroll
    for (int i = 0; i < 4; i++) {
        m[i] = -1e30f; l[i] = 0.0f;
        #pragma unroll
        for (int j = 0; j < 8; j++) acc[i][j] = 0.0f;
    }

    for (int kt = 0; kt <= qt; kt++) {
        // --- load K tile into KV ---
        {
            const float* Kg = g_K + ((size_t)b * T_ + kt * 64) * DH;
            #pragma unroll
            for (int l2 = 0; l2 < 8; l2++) {
                int lin = tid + l2 * 128;
                int r = lin >> 4, c4 = lin & 15;
                *(float4*)&KV[r * PAD + c4 * 4] = ((const float4*)Kg)[r * 16 + c4];
            }
        }
        __syncthreads();

        // --- S = Q K^T (per-thread 4x8 tile) ---
        float s[4][8];
        #pragma unroll
        for (int i = 0; i < 4; i++)
            #pragma unroll
            for (int j = 0; j < 8; j++) s[i][j] = 0.0f;

        #pragma unroll 8
        for (int d = 0; d < 64; d++) {
            float qv[4], kv[8];
            #pragma unroll
            for (int i = 0; i < 4; i++) qv[i] = Qs[(ty*4 + i) * PAD + d];
            #pragma unroll
            for (int j = 0; j < 8; j++) kv[j] = KV[(j*8 + tx) * PAD + d];
            #pragma unroll
            for (int i = 0; i < 4; i++)
                #pragma unroll
                for (int j = 0; j < 8; j++)
                    s[i][j] = fmaf(qv[i], kv[j], s[i][j]);
        }

        // --- causal mask on diagonal tile ---
        if (kt == qt) {
            #pragma unroll
            for (int i = 0; i < 4; i++) {
                int rr = ty*4 + i;
                #pragma unroll
                for (int j = 0; j < 8; j++) {
                    int cc = j*8 + tx;
                    if (cc > rr) s[i][j] = -1e30f;
                }
            }
        }

        // --- online softmax update ---
        float p[4][8];
        #pragma unroll
        for (int i = 0; i < 4; i++) {
            float mx = s[i][0];
            #pragma unroll
            for (int j = 1; j < 8; j++) mx = fmaxf(mx, s[i][j]);
            mx = fmaxf(mx, __shfl_xor_sync(0xffffffffu, mx, 1));
            mx = fmaxf(mx, __shfl_xor_sync(0xffffffffu, mx, 2));
            mx = fmaxf(mx, __shfl_xor_sync(0xffffffffu, mx, 4));

            float nm = fmaxf(m[i], mx);
            float f  = __expf(m[i] - nm);
            m[i] = nm;

            float rs = 0.0f;
            #pragma unroll
            for (int j = 0; j < 8; j++) {
                float pv = __expf(s[i][j] - nm);
                p[i][j] = pv;
                rs += pv;
            }
            rs += __shfl_xor_sync(0xffffffffu, rs, 1);
            rs += __shfl_xor_sync(0xffffffffu, rs, 2);
            rs += __shfl_xor_sync(0xffffffffu, rs, 4);

            l[i] = l[i] * f + rs;
            #pragma unroll
            for (int j = 0; j < 8; j++) acc[i][j] *= f;
        }
        __syncthreads();   // K reads done; Ps reads from prev iter done

        // --- write P to smem; load V tile into KV ---
        #pragma unroll
        for (int i = 0; i < 4; i++)
            #pragma unroll
            for (int j = 0; j < 8; j++)
                Ps[(ty*4 + i) * PAD + (j*8 + tx)] = p[i][j];
        {
            const float* Vg = g_V + ((size_t)b * T_ + kt * 64) * DH;
            #pragma unroll
            for (int l2 = 0; l2 < 8; l2++) {
                int lin = tid + l2 * 128;
                int r = lin >> 4, c4 = lin & 15;
                *(float4*)&KV[r * PAD + c4 * 4] = ((const float4*)Vg)[r * 16 + c4];
            }
        }
        __syncthreads();

        // --- O += P V (per-thread 4 rows x 8 d-cols) ---
        #pragma unroll 8
        for (int k = 0; k < 64; k++) {
            float pr[4], vv[8];
            #pragma unroll
            for (int i = 0; i < 4; i++) pr[i] = Ps[(ty*4 + i) * PAD + k];
            #pragma unroll
            for (int j = 0; j < 8; j++) vv[j] = KV[k * PAD + (j*8 + tx)];
            #pragma unroll
            for (int i = 0; i < 4; i++)
                #pragma unroll
                for (int j = 0; j < 8; j++)
                    acc[i][j] = fmaf(pr[i], vv[j], acc[i][j]);
        }
        __syncthreads();   // PV reads done before next K overwrite
    }

    // --- epilogue: normalize and store ---
    #pragma unroll
    for (int i = 0; i < 4; i++) {
        float inv = 1.0f / l[i];
        size_t row = (size_t)b * T_ + q0 + ty*4 + i;
        #pragma unroll
        for (int j = 0; j < 8; j++)
            out[row * DH + (j*8 + tx)] = acc[i][j] * inv;
    }
}

// ---------------------------------------------------------------------------
extern "C" void kernel_launch(void* const* d_in, const int* in_sizes, int n_in,
                              void* d_out, int out_size)
{
    const float* x  = (const float*)d_in[0];
    const float* Wq = (const float*)d_in[1];
    const float* Wk = (const float*)d_in[2];
    const float* Wv = (const float*)d_in[3];
    float* out = (float*)d_out;

    proj_kernel<<<BT / 64, 256>>>(x, Wq, Wk, Wv);

    cudaFuncSetAttribute(attn_kernel,
                         cudaFuncAttributeMaxDynamicSharedMemorySize,
                         ATTN_SMEM_BYTES);
    attn_kernel<<<dim3(T_ / 64, B_), 128, ATTN_SMEM_BYTES>>>(out);
}

// round 4
// speedup vs baseline: 1.0619x; 1.0619x over previous
#include <cuda_runtime.h>

#define B_  8
#define T_  2048
#define DM  1024
#define DH  64
#define BT  (B_*T_)

// Scratch: Q and V natural [b*T + t][64]; K transposed [b][d][t]
__device__ float g_Q [BT * DH];
__device__ float g_Kt[B_ * DH * T_];
__device__ float g_V [BT * DH];

typedef unsigned long long u64;

#define FMA2(d,a,b,c) asm("fma.rn.f32x2 %0, %1, %2, %3;" : "=l"(d) : "l"(a), "l"(b), "l"(c))
#define MUL2(d,a,b)   asm("mul.rn.f32x2 %0, %1, %2;"     : "=l"(d) : "l"(a), "l"(b))
#define PACK2(d,x)    asm("mov.b64 %0, {%1, %1};"        : "=l"(d) : "f"(x))
#define UNPK2(lo,hi,v) asm("mov.b64 {%0, %1}, %2;"       : "=f"(lo), "=f"(hi) : "l"(v))

__device__ __forceinline__ float f4c(const float4& v, int k) {
    switch (k) { case 0: return v.x; case 1: return v.y; case 2: return v.z; default: return v.w; }
}

// ---------------------------------------------------------------------------
// Kernel 1: fused QKV projection (f32x2).
// Grid: 256 blocks, 256 threads. Block tile [64 rows x 192 cols], k-tile 32.
// Thread tile: 4 rows x 12 cols (= 6 packed col-pairs).
// ---------------------------------------------------------------------------
#define XS 36     // xs row stride (floats): 16B-aligned vec reads
#define WS 196    // ws row stride

__global__ __launch_bounds__(256) void proj_kernel(
    const float* __restrict__ x,
    const float* __restrict__ Wq,
    const float* __restrict__ Wk,
    const float* __restrict__ Wv)
{
    __shared__ float xs[64 * XS];
    __shared__ float ws[32 * WS];

    const int tid = threadIdx.x;
    const int tx  = tid & 15;       // cols tx*12 .. +11
    const int ty  = tid >> 4;       // rows ty*4 .. +3
    const int row0 = blockIdx.x * 64;

    u64 acc[4][6];
    #pragma unroll
    for (int i = 0; i < 4; i++)
        #pragma unroll
        for (int p = 0; p < 6; p++) acc[i][p] = 0ull;

    for (int kk0 = 0; kk0 < DM; kk0 += 32) {
        // x tile [64 x 32]: 512 float4
        #pragma unroll
        for (int lo = 0; lo < 2; lo++) {
            int lin = tid + lo * 256;
            int r = lin >> 3, c4 = lin & 7;
            float4 v = ((const float4*)x)[(size_t)(row0 + r) * (DM/4) + (kk0 >> 2) + c4];
            *(float4*)&xs[r * XS + c4 * 4] = v;
        }
        // w tile [32 x 192]: 1536 float4
        #pragma unroll
        for (int lo = 0; lo < 6; lo++) {
            int lin = tid + lo * 256;
            int r = lin / 48, c4 = lin % 48;
            int mat = c4 >> 4, cc = c4 & 15;
            const float* Wp = (mat == 0) ? Wq : (mat == 1) ? Wk : Wv;
            float4 v = ((const float4*)Wp)[(size_t)(kk0 + r) * (DH/4) + cc];
            *(float4*)&ws[r * WS + c4 * 4] = v;
        }
        __syncthreads();

        #pragma unroll 2
        for (int k4 = 0; k4 < 8; k4++) {
            float4 xq[4];
            #pragma unroll
            for (int i = 0; i < 4; i++)
                xq[i] = *(const float4*)&xs[(ty*4 + i) * XS + k4 * 4];
            #pragma unroll
            for (int kk = 0; kk < 4; kk++) {
                const float* wr = &ws[(k4*4 + kk) * WS + tx * 12];
                ulonglong2 wa = *(const ulonglong2*)(wr);
                ulonglong2 wb = *(const ulonglong2*)(wr + 4);
                ulonglong2 wc = *(const ulonglong2*)(wr + 8);
                u64 wp0 = wa.x, wp1 = wa.y, wp2 = wb.x, wp3 = wb.y, wp4 = wc.x, wp5 = wc.y;
                #pragma unroll
                for (int i = 0; i < 4; i++) {
                    u64 xb; PACK2(xb, f4c(xq[i], kk));
                    FMA2(acc[i][0], xb, wp0, acc[i][0]);
                    FMA2(acc[i][1], xb, wp1, acc[i][1]);
                    FMA2(acc[i][2], xb, wp2, acc[i][2]);
                    FMA2(acc[i][3], xb, wp3, acc[i][3]);
                    FMA2(acc[i][4], xb, wp4, acc[i][4]);
                    FMA2(acc[i][5], xb, wp5, acc[i][5]);
                }
            }
        }
        __syncthreads();
    }

    // epilogue: route pairs to Q (natural), K (transposed), V (natural)
    const int c0 = tx * 12;
    #pragma unroll
    for (int i = 0; i < 4; i++) {
        int row = row0 + ty*4 + i;
        int b = row >> 11, t = row & (T_ - 1);
        #pragma unroll
        for (int p = 0; p < 6; p++) {
            float lo, hi; UNPK2(lo, hi, acc[i][p]);
            int c = c0 + 2*p;
            #pragma unroll
            for (int e = 0; e < 2; e++) {
                int cc = c + e;
                float v = e ? hi : lo;
                if (cc < 64)        g_Q [(size_t)row * DH + cc] = v;
                else if (cc < 128)  g_Kt[((size_t)b * DH + (cc - 64)) * T_ + t] = v;
                else                g_V [(size_t)row * DH + (cc - 128)] = v;
            }
        }
    }
}

// ---------------------------------------------------------------------------
// Kernel 2: causal flash attention (f32x2).
// Grid: (32, 8), 128 threads. BQ=BK=64.
// Thread: 4 q-rows (ty) x 8 cols at {tx*4..+3} and {32+tx*4..+3}.
// ---------------------------------------------------------------------------
#define QS 68
#define ATTN_SMEM_BYTES (3 * 64 * QS * (int)sizeof(float))

__global__ __launch_bounds__(128) void attn_kernel(float* __restrict__ out)
{
    extern __shared__ float sm[];
    float* Qs = sm;                // [r][d] natural, prescaled
    float* KV = sm + 64 * QS;      // K^T [d][col], then V [k][d]
    float* Ps = sm + 2 * 64 * QS;  // [r][k]

    const int tid = threadIdx.x;
    const int tx  = tid & 7;
    const int ty  = tid >> 3;
    const int qt  = gridDim.x - 1 - blockIdx.x;
    const int b   = blockIdx.y;
    const int q0  = qt * 64;
    const int cA  = tx * 4;
    const int cB  = 32 + tx * 4;

    // load Q (prescaled by 1/8)
    {
        const float* Qg = g_Q + ((size_t)b * T_ + q0) * DH;
        #pragma unroll
        for (int lo = 0; lo < 8; lo++) {
            int lin = tid + lo * 128;
            int r = lin >> 4, c4 = lin & 15;
            float4 v = ((const float4*)Qg)[r * 16 + c4];
            v.x *= 0.125f; v.y *= 0.125f; v.z *= 0.125f; v.w *= 0.125f;
            *(float4*)&Qs[r * QS + c4 * 4] = v;
        }
    }

    float mrow[4], lsum[4];
    u64 oA[4][2], oB[4][2];
    #pragma unroll
    for (int i = 0; i < 4; i++) {
        mrow[i] = -1e30f; lsum[i] = 0.0f;
        oA[i][0] = oA[i][1] = oB[i][0] = oB[i][1] = 0ull;
    }

    for (int kt = 0; kt <= qt; kt++) {
        // --- load K^T tile [d][col] from g_Kt (coalesced, natural store) ---
        {
            const float* Kg = g_Kt + (size_t)b * DH * T_ + kt * 64;
            #pragma unroll
            for (int lo = 0; lo < 8; lo++) {
                int lin = tid + lo * 128;
                int d = lin >> 4, c4 = lin & 15;
                *(float4*)&KV[d * QS + c4 * 4] =
                    *(const float4*)&Kg[(size_t)d * T_ + c4 * 4];
            }
        }
        __syncthreads();

        // --- S = Q K^T, packed col-pairs ---
        u64 sA[4][2], sB[4][2];
        #pragma unroll
        for (int i = 0; i < 4; i++) { sA[i][0]=sA[i][1]=sB[i][0]=sB[i][1]=0ull; }

        #pragma unroll 4
        for (int d4 = 0; d4 < 16; d4++) {
            float4 q4[4];
            #pragma unroll
            for (int i = 0; i < 4; i++)
                q4[i] = *(const float4*)&Qs[(ty*4 + i) * QS + d4 * 4];
            #pragma unroll
            for (int dd = 0; dd < 4; dd++) {
                const float* kr = &KV[(d4*4 + dd) * QS + cA];
                ulonglong2 ka = *(const ulonglong2*)kr;
                ulonglong2 kb = *(const ulonglong2*)(kr + 32);
                #pragma unroll
                for (int i = 0; i < 4; i++) {
                    u64 qb; PACK2(qb, f4c(q4[i], dd));
                    FMA2(sA[i][0], qb, ka.x, sA[i][0]);
                    FMA2(sA[i][1], qb, ka.y, sA[i][1]);
                    FMA2(sB[i][0], qb, kb.x, sB[i][0]);
                    FMA2(sB[i][1], qb, kb.y, sB[i][1]);
                }
            }
        }

        // --- unpack, mask, online softmax ---
        float s[4][8], p[4][8];
        #pragma unroll
        for (int i = 0; i < 4; i++) {
            UNPK2(s[i][0], s[i][1], sA[i][0]);
            UNPK2(s[i][2], s[i][3], sA[i][1]);
            UNPK2(s[i][4], s[i][5], sB[i][0]);
            UNPK2(s[i][6], s[i][7], sB[i][1]);
        }
        if (kt == qt) {
            #pragma unroll
            for (int i = 0; i < 4; i++) {
                int rr = ty*4 + i;
                #pragma unroll
                for (int j = 0; j < 4; j++) {
                    if (cA + j > rr) s[i][j]     = -1e30f;
                    if (cB + j > rr) s[i][4 + j] = -1e30f;
                }
            }
        }
        #pragma unroll
        for (int i = 0; i < 4; i++) {
            float mx = s[i][0];
            #pragma unroll
            for (int j = 1; j < 8; j++) mx = fmaxf(mx, s[i][j]);
            mx = fmaxf(mx, __shfl_xor_sync(0xffffffffu, mx, 1));
            mx = fmaxf(mx, __shfl_xor_sync(0xffffffffu, mx, 2));
            mx = fmaxf(mx, __shfl_xor_sync(0xffffffffu, mx, 4));

            float nm = fmaxf(mrow[i], mx);
            float f  = __expf(mrow[i] - nm);
            mrow[i] = nm;

            float rs = 0.0f;
            #pragma unroll
            for (int j = 0; j < 8; j++) {
                float pv = __expf(s[i][j] - nm);
                p[i][j] = pv;
                rs += pv;
            }
            rs += __shfl_xor_sync(0xffffffffu, rs, 1);
            rs += __shfl_xor_sync(0xffffffffu, rs, 2);
            rs += __shfl_xor_sync(0xffffffffu, rs, 4);
            lsum[i] = lsum[i] * f + rs;

            u64 fb; PACK2(fb, f);
            MUL2(oA[i][0], oA[i][0], fb);
            MUL2(oA[i][1], oA[i][1], fb);
            MUL2(oB[i][0], oB[i][0], fb);
            MUL2(oB[i][1], oB[i][1], fb);
        }
        __syncthreads();  // K reads + prev P reads complete

        // --- store P; load V (reuses KV, natural [k][d]) ---
        #pragma unroll
        for (int i = 0; i < 4; i++) {
            int rr = ty*4 + i;
            *(float4*)&Ps[rr * QS + cA] = make_float4(p[i][0], p[i][1], p[i][2], p[i][3]);
            *(float4*)&Ps[rr * QS + cB] = make_float4(p[i][4], p[i][5], p[i][6], p[i][7]);
        }
        {
            const float* Vg = g_V + ((size_t)b * T_ + kt * 64) * DH;
            #pragma unroll
            for (int lo = 0; lo < 8; lo++) {
                int lin = tid + lo * 128;
                int r = lin >> 4, c4 = lin & 15;
                *(float4*)&KV[r * QS + c4 * 4] = ((const float4*)Vg)[r * 16 + c4];
            }
        }
        __syncthreads();

        // --- O += P V, packed d-pairs ---
        #pragma unroll 4
        for (int k4 = 0; k4 < 16; k4++) {
            float4 p4[4];
            #pragma unroll
            for (int i = 0; i < 4; i++)
                p4[i] = *(const float4*)&Ps[(ty*4 + i) * QS + k4 * 4];
            #pragma unroll
            for (int kk = 0; kk < 4; kk++) {
                const float* vr = &KV[(k4*4 + kk) * QS + cA];
                ulonglong2 va = *(const ulonglong2*)vr;
                ulonglong2 vb = *(const ulonglong2*)(vr + 32);
                #pragma unroll
                for (int i = 0; i < 4; i++) {
                    u64 pb; PACK2(pb, f4c(p4[i], kk));
                    FMA2(oA[i][0], pb, va.x, oA[i][0]);
                    FMA2(oA[i][1], pb, va.y, oA[i][1]);
                    FMA2(oB[i][0], pb, vb.x, oB[i][0]);
                    FMA2(oB[i][1], pb, vb.y, oB[i][1]);
                }
            }
        }
        __syncthreads();  // V/P reads complete before next overwrite
    }

    // --- epilogue ---
    #pragma unroll
    for (int i = 0; i < 4; i++) {
        float inv = 1.0f / lsum[i];
        size_t row = (size_t)b * T_ + q0 + ty*4 + i;
        float a0,a1,a2,a3;
        UNPK2(a0, a1, oA[i][0]); UNPK2(a2, a3, oA[i][1]);
        *(float4*)&out[row * DH + cA] = make_float4(a0*inv, a1*inv, a2*inv, a3*inv);
        UNPK2(a0, a1, oB[i][0]); UNPK2(a2, a3, oB[i][1]);
        *(float4*)&out[row * DH + cB] = make_float4(a0*inv, a1*inv, a2*inv, a3*inv);
    }
}

// ---------------------------------------------------------------------------
extern "C" void kernel_launch(void* const* d_in, const int* in_sizes, int n_in,
                              void* d_out, int out_size)
{
    const float* x  = (const float*)d_in[0];
    const float* Wq = (const float*)d_in[1];
    const float* Wk = (const float*)d_in[2];
    const float* Wv = (const float*)d_in[3];
    float* out = (float*)d_out;

    proj_kernel<<<BT / 64, 256>>>(x, Wq, Wk, Wv);

    cudaFuncSetAttribute(attn_kernel,
                         cudaFuncAttributeMaxDynamicSharedMemorySize,
                         ATTN_SMEM_BYTES);
    attn_kernel<<<dim3(T_ / 64, B_), 128, ATTN_SMEM_BYTES>>>(out);
}

// round 9
// speedup vs baseline: 1.2350x; 1.1629x over previous
#include <cuda_runtime.h>
#include <cuda_bf16.h>
#include <cstdint>

#define B_  8
#define T_  2048
#define DM  1024
#define DH  64
#define BT  (B_*T_)

// Scratch: Q and V natural [b*T + t][64]; K transposed [b][d][t]
__device__ float g_Q [BT * DH];
__device__ float g_Kt[B_ * DH * T_];
__device__ float g_V [BT * DH];
// Pre-split, pre-transposed weights: [n][k], n: 0-63 Q, 64-127 K, 128-191 V
__device__ __nv_bfloat16 g_Wt_hi[192 * DM];
__device__ __nv_bfloat16 g_Wt_lo[192 * DM];

typedef unsigned long long u64;

// ---------------- f32x2 helpers (attention kernel) ----------------
#define FMA2(d,a,b,c) asm("fma.rn.f32x2 %0, %1, %2, %3;" : "=l"(d) : "l"(a), "l"(b), "l"(c))
#define MUL2(d,a,b)   asm("mul.rn.f32x2 %0, %1, %2;"     : "=l"(d) : "l"(a), "l"(b))
#define PACK2(d,x)    asm("mov.b64 %0, {%1, %1};"        : "=l"(d) : "f"(x))
#define UNPK2(lo,hi,v) asm("mov.b64 {%0, %1}, %2;"       : "=f"(lo), "=f"(hi) : "l"(v))

__device__ __forceinline__ float f4c(const float4& v, int k) {
    switch (k) { case 0: return v.x; case 1: return v.y; case 2: return v.z; default: return v.w; }
}

// ---------------- mma.sync helper ----------------
__device__ __forceinline__ void mma_bf16(float* c, const uint32_t* a, const uint32_t* b) {
    asm volatile(
        "mma.sync.aligned.m16n8k16.row.col.f32.bf16.bf16.f32 "
        "{%0,%1,%2,%3}, {%4,%5,%6,%7}, {%8,%9}, {%0,%1,%2,%3};\n"
        : "+f"(c[0]), "+f"(c[1]), "+f"(c[2]), "+f"(c[3])
        : "r"(a[0]), "r"(a[1]), "r"(a[2]), "r"(a[3]), "r"(b[0]), "r"(b[1]));
}

__device__ __forceinline__ uint32_t pack_bf2(__nv_bfloat16 a, __nv_bfloat16 b) {
    __nv_bfloat162 t(a, b);
    return *reinterpret_cast<uint32_t*>(&t);
}

// ---------------------------------------------------------------------------
// Kernel 0: split + transpose W -> g_Wt_hi/lo [n][k]
// ---------------------------------------------------------------------------
__global__ void wt_prep(const float* __restrict__ Wq,
                        const float* __restrict__ Wk,
                        const float* __restrict__ Wv)
{
    int n = blockIdx.x;  // 0..191
    const float* W = (n < 64) ? Wq : (n < 128) ? Wk : Wv;
    int nn = n & 63;
    for (int k = threadIdx.x; k < DM; k += blockDim.x) {
        float v = W[(size_t)k * 64 + nn];
        __nv_bfloat16 h = __float2bfloat16(v);
        __nv_bfloat16 l = __float2bfloat16(v - __bfloat162float(h));
        g_Wt_hi[(size_t)n * DM + k] = h;
        g_Wt_lo[(size_t)n * DM + k] = l;
    }
}

// ---------------------------------------------------------------------------
// Kernel 1: QKV projection via mma.sync bf16 hi/lo (3-MMA split).
// Grid 128 CTAs x 256 threads (8 warps, 4m x 2n).
// CTA tile: M=128 x N=192, K=1024 in 16 k-tiles of 64.
// Warp tile: M=32 x N=96 -> acc[2 mt][12 nf][4].
// ---------------------------------------------------------------------------
#define PITCH 144                    // smem row pitch in BYTES (72 bf16)
#define SA_HI 0
#define SA_LO (SA_HI + 128 * PITCH)  // 18432
#define SB_HI (SA_LO + 128 * PITCH)  // 36864
#define SB_LO (SB_HI + 192 * PITCH)  // 64512
#define PROJ_SMEM (SB_LO + 192 * PITCH)  // 92160 B

__global__ __launch_bounds__(256) void proj_kernel(const float* __restrict__ x)
{
    extern __shared__ char smem[];
    const int tid  = threadIdx.x;
    const int lane = tid & 31;
    const int wid  = tid >> 5;
    const int mw   = wid >> 1;            // 0..3
    const int nw   = wid & 1;             // 0..1
    const int row0 = blockIdx.x * 128;

    const int lr = lane >> 2;             // 0..7
    const int lc = lane & 3;              // 0..3

    float acc[2][12][4];
    #pragma unroll
    for (int mt = 0; mt < 2; mt++)
        #pragma unroll
        for (int nf = 0; nf < 12; nf++)
            #pragma unroll
            for (int r = 0; r < 4; r++) acc[mt][nf][r] = 0.0f;

    for (int kt = 0; kt < 16; kt++) {
        const int k0 = kt * 64;

        // --- stage x tile [128 x 64] fp32 -> hi/lo bf16 ---
        #pragma unroll
        for (int i = 0; i < 8; i++) {
            int lin = tid + i * 256;            // 0..2047
            int r = lin >> 4, c4 = (lin & 15) * 4;
            float4 v = *(const float4*)&x[(size_t)(row0 + r) * DM + k0 + c4];
            __nv_bfloat16 h0 = __float2bfloat16(v.x), h1 = __float2bfloat16(v.y);
            __nv_bfloat16 h2 = __float2bfloat16(v.z), h3 = __float2bfloat16(v.w);
            __nv_bfloat16 l0 = __float2bfloat16(v.x - __bfloat162float(h0));
            __nv_bfloat16 l1 = __float2bfloat16(v.y - __bfloat162float(h1));
            __nv_bfloat16 l2 = __float2bfloat16(v.z - __bfloat162float(h2));
            __nv_bfloat16 l3 = __float2bfloat16(v.w - __bfloat162float(h3));
            int off = r * PITCH + c4 * 2;
            *(uint2*)(smem + SA_HI + off) = make_uint2(pack_bf2(h0, h1), pack_bf2(h2, h3));
            *(uint2*)(smem + SA_LO + off) = make_uint2(pack_bf2(l0, l1), pack_bf2(l2, l3));
        }
        // --- stage W tiles [192 x 64] bf16 hi/lo (pre-split, [n][k]) ---
        #pragma unroll
        for (int i = 0; i < 6; i++) {
            int lin = tid + i * 256;            // 0..1535
            int n = lin >> 3, c8 = (lin & 7) * 8;
            int off = n * PITCH + c8 * 2;
            *(uint4*)(smem + SB_HI + off) = *(const uint4*)&g_Wt_hi[(size_t)n * DM + k0 + c8];
            *(uint4*)(smem + SB_LO + off) = *(const uint4*)&g_Wt_lo[(size_t)n * DM + k0 + c8];
        }
        __syncthreads();

        // --- MMA phase: 4 k-steps of 16 ---
        #pragma unroll
        for (int ks = 0; ks < 4; ks++) {
            uint32_t ah[2][4], al[2][4];
            #pragma unroll
            for (int mt = 0; mt < 2; mt++) {
                int abase = (mw * 32 + mt * 16 + lr) * PITCH + ks * 32 + lc * 4;
                ah[mt][0] = *(const uint32_t*)(smem + SA_HI + abase);
                ah[mt][1] = *(const uint32_t*)(smem + SA_HI + abase + 8 * PITCH);
                ah[mt][2] = *(const uint32_t*)(smem + SA_HI + abase + 16);
                ah[mt][3] = *(const uint32_t*)(smem + SA_HI + abase + 8 * PITCH + 16);
                al[mt][0] = *(const uint32_t*)(smem + SA_LO + abase);
                al[mt][1] = *(const uint32_t*)(smem + SA_LO + abase + 8 * PITCH);
                al[mt][2] = *(const uint32_t*)(smem + SA_LO + abase + 16);
                al[mt][3] = *(const uint32_t*)(smem + SA_LO + abase + 8 * PITCH + 16);
            }
            #pragma unroll
            for (int nf = 0; nf < 12; nf++) {
                int bbase = (nw * 96 + nf * 8 + lr) * PITCH + ks * 32 + lc * 4;
                uint32_t bh[2], bl[2];
                bh[0] = *(const uint32_t*)(smem + SB_HI + bbase);
                bh[1] = *(const uint32_t*)(smem + SB_HI + bbase + 16);
                bl[0] = *(const uint32_t*)(smem + SB_LO + bbase);
                bl[1] = *(const uint32_t*)(smem + SB_LO + bbase + 16);
                mma_bf16(acc[0][nf], ah[0], bh);
                mma_bf16(acc[1][nf], ah[1], bh);
                mma_bf16(acc[0][nf], al[0], bh);
                mma_bf16(acc[1][nf], al[1], bh);
                mma_bf16(acc[0][nf], ah[0], bl);
                mma_bf16(acc[1][nf], ah[1], bl);
            }
        }
        __syncthreads();
    }

    // --- epilogue: fragments -> g_Q / g_Kt / g_V ---
    #pragma unroll
    for (int mt = 0; mt < 2; mt++) {
        #pragma unroll
        for (int nf = 0; nf < 12; nf++) {
            int c  = nw * 96 + nf * 8 + 2 * lc;
            int r1 = row0 + mw * 32 + mt * 16 + lr;
            int r2 = r1 + 8;
            float v0 = acc[mt][nf][0], v1 = acc[mt][nf][1];
            float v2 = acc[mt][nf][2], v3 = acc[mt][nf][3];
            if (c < 64) {
                *(float2*)&g_Q[(size_t)r1 * DH + c] = make_float2(v0, v1);
                *(float2*)&g_Q[(size_t)r2 * DH + c] = make_float2(v2, v3);
            } else if (c < 128) {
                int cc = c - 64;
                int b1 = r1 >> 11, t1 = r1 & (T_ - 1);
                int b2 = r2 >> 11, t2 = r2 & (T_ - 1);
                g_Kt[((size_t)b1 * DH + cc)     * T_ + t1] = v0;
                g_Kt[((size_t)b1 * DH + cc + 1) * T_ + t1] = v1;
                g_Kt[((size_t)b2 * DH + cc)     * T_ + t2] = v2;
                g_Kt[((size_t)b2 * DH + cc + 1) * T_ + t2] = v3;
            } else {
                int cc = c - 128;
                *(float2*)&g_V[(size_t)r1 * DH + cc] = make_float2(v0, v1);
                *(float2*)&g_V[(size_t)r2 * DH + cc] = make_float2(v2, v3);
            }
        }
    }
}

// ---------------------------------------------------------------------------
// Kernel 2: causal flash attention (f32x2) — UNCHANGED from R4 (passing).
// ---------------------------------------------------------------------------
#define QS 68
#define ATTN_SMEM_BYTES (3 * 64 * QS * (int)sizeof(float))

__global__ __launch_bounds__(128) void attn_kernel(float* __restrict__ out)
{
    extern __shared__ float sm[];
    float* Qs = sm;
    float* KV = sm + 64 * QS;
    float* Ps = sm + 2 * 64 * QS;

    const int tid = threadIdx.x;
    const int tx  = tid & 7;
    const int ty  = tid >> 3;
    const int qt  = gridDim.x - 1 - blockIdx.x;
    const int b   = blockIdx.y;
    const int q0  = qt * 64;
    const int cA  = tx * 4;
    const int cB  = 32 + tx * 4;

    {
        const float* Qg = g_Q + ((size_t)b * T_ + q0) * DH;
        #pragma unroll
        for (int lo = 0; lo < 8; lo++) {
            int lin = tid + lo * 128;
            int r = lin >> 4, c4 = lin & 15;
            float4 v = ((const float4*)Qg)[r * 16 + c4];
            v.x *= 0.125f; v.y *= 0.125f; v.z *= 0.125f; v.w *= 0.125f;
            *(float4*)&Qs[r * QS + c4 * 4] = v;
        }
    }

    float mrow[4], lsum[4];
    u64 oA[4][2], oB[4][2];
    #pragma unroll
    for (int i = 0; i < 4; i++) {
        mrow[i] = -1e30f; lsum[i] = 0.0f;
        oA[i][0] = oA[i][1] = oB[i][0] = oB[i][1] = 0ull;
    }

    for (int kt = 0; kt <= qt; kt++) {
        {
            const float* Kg = g_Kt + (size_t)b * DH * T_ + kt * 64;
            #pragma unroll
            for (int lo = 0; lo < 8; lo++) {
                int lin = tid + lo * 128;
                int d = lin >> 4, c4 = lin & 15;
                *(float4*)&KV[d * QS + c4 * 4] =
                    *(const float4*)&Kg[(size_t)d * T_ + c4 * 4];
            }
        }
        __syncthreads();

        u64 sA[4][2], sB[4][2];
        #pragma unroll
        for (int i = 0; i < 4; i++) { sA[i][0]=sA[i][1]=sB[i][0]=sB[i][1]=0ull; }

        #pragma unroll 4
        for (int d4 = 0; d4 < 16; d4++) {
            float4 q4[4];
            #pragma unroll
            for (int i = 0; i < 4; i++)
                q4[i] = *(const float4*)&Qs[(ty*4 + i) * QS + d4 * 4];
            #pragma unroll
            for (int dd = 0; dd < 4; dd++) {
                const float* kr = &KV[(d4*4 + dd) * QS + cA];
                ulonglong2 ka = *(const ulonglong2*)kr;
                ulonglong2 kb = *(const ulonglong2*)(kr + 32);
                #pragma unroll
                for (int i = 0; i < 4; i++) {
                    u64 qb; PACK2(qb, f4c(q4[i], dd));
                    FMA2(sA[i][0], qb, ka.x, sA[i][0]);
                    FMA2(sA[i][1], qb, ka.y, sA[i][1]);
                    FMA2(sB[i][0], qb, kb.x, sB[i][0]);
                    FMA2(sB[i][1], qb, kb.y, sB[i][1]);
                }
            }
        }

        float s[4][8], p[4][8];
        #pragma unroll
        for (int i = 0; i < 4; i++) {
            UNPK2(s[i][0], s[i][1], sA[i][0]);
            UNPK2(s[i][2], s[i][3], sA[i][1]);
            UNPK2(s[i][4], s[i][5], sB[i][0]);
            UNPK2(s[i][6], s[i][7], sB[i][1]);
        }
        if (kt == qt) {
            #pragma unroll
            for (int i = 0; i < 4; i++) {
                int rr = ty*4 + i;
                #pragma unroll
                for (int j = 0; j < 4; j++) {
                    if (cA + j > rr) s[i][j]     = -1e30f;
                    if (cB + j > rr) s[i][4 + j] = -1e30f;
                }
            }
        }
        #pragma unroll
        for (int i = 0; i < 4; i++) {
            float mx = s[i][0];
            #pragma unroll
            for (int j = 1; j < 8; j++) mx = fmaxf(mx, s[i][j]);
            mx = fmaxf(mx, __shfl_xor_sync(0xffffffffu, mx, 1));
            mx = fmaxf(mx, __shfl_xor_sync(0xffffffffu, mx, 2));
            mx = fmaxf(mx, __shfl_xor_sync(0xffffffffu, mx, 4));

            float nm = fmaxf(mrow[i], mx);
            float f  = __expf(mrow[i] - nm);
            mrow[i] = nm;

            float rs = 0.0f;
            #pragma unroll
            for (int j = 0; j < 8; j++) {
                float pv = __expf(s[i][j] - nm);
                p[i][j] = pv;
                rs += pv;
            }
            rs += __shfl_xor_sync(0xffffffffu, rs, 1);
            rs += __shfl_xor_sync(0xffffffffu, rs, 2);
            rs += __shfl_xor_sync(0xffffffffu, rs, 4);
            lsum[i] = lsum[i] * f + rs;

            u64 fb; PACK2(fb, f);
            MUL2(oA[i][0], oA[i][0], fb);
            MUL2(oA[i][1], oA[i][1], fb);
            MUL2(oB[i][0], oB[i][0], fb);
            MUL2(oB[i][1], oB[i][1], fb);
        }
        __syncthreads();

        #pragma unroll
        for (int i = 0; i < 4; i++) {
            int rr = ty*4 + i;
            *(float4*)&Ps[rr * QS + cA] = make_float4(p[i][0], p[i][1], p[i][2], p[i][3]);
            *(float4*)&Ps[rr * QS + cB] = make_float4(p[i][4], p[i][5], p[i][6], p[i][7]);
        }
        {
            const float* Vg = g_V + ((size_t)b * T_ + kt * 64) * DH;
            #pragma unroll
            for (int lo = 0; lo < 8; lo++) {
                int lin = tid + lo * 128;
                int r = lin >> 4, c4 = lin & 15;
                *(float4*)&KV[r * QS + c4 * 4] = ((const float4*)Vg)[r * 16 + c4];
            }
        }
        __syncthreads();

        #pragma unroll 4
        for (int k4 = 0; k4 < 16; k4++) {
            float4 p4[4];
            #pragma unroll
            for (int i = 0; i < 4; i++)
                p4[i] = *(const float4*)&Ps[(ty*4 + i) * QS + k4 * 4];
            #pragma unroll
            for (int kk = 0; kk < 4; kk++) {
                const float* vr = &KV[(k4*4 + kk) * QS + cA];
                ulonglong2 va = *(const ulonglong2*)vr;
                ulonglong2 vb = *(const ulonglong2*)(vr + 32);
                #pragma unroll
                for (int i = 0; i < 4; i++) {
                    u64 pb; PACK2(pb, f4c(p4[i], kk));
                    FMA2(oA[i][0], pb, va.x, oA[i][0]);
                    FMA2(oA[i][1], pb, va.y, oA[i][1]);
                    FMA2(oB[i][0], pb, vb.x, oB[i][0]);
                    FMA2(oB[i][1], pb, vb.y, oB[i][1]);
                }
            }
        }
        __syncthreads();
    }

    #pragma unroll
    for (int i = 0; i < 4; i++) {
        float inv = 1.0f / lsum[i];
        size_t row = (size_t)b * T_ + q0 + ty*4 + i;
        float a0,a1,a2,a3;
        UNPK2(a0, a1, oA[i][0]); UNPK2(a2, a3, oA[i][1]);
        *(float4*)&out[row * DH + cA] = make_float4(a0*inv, a1*inv, a2*inv, a3*inv);
        UNPK2(a0, a1, oB[i][0]); UNPK2(a2, a3, oB[i][1]);
        *(float4*)&out[row * DH + cB] = make_float4(a0*inv, a1*inv, a2*inv, a3*inv);
    }
}

// ---------------------------------------------------------------------------
extern "C" void kernel_launch(void* const* d_in, const int* in_sizes, int n_in,
                              void* d_out, int out_size)
{
    const float* x  = (const float*)d_in[0];
    const float* Wq = (const float*)d_in[1];
    const float* Wk = (const float*)d_in[2];
    const float* Wv = (const float*)d_in[3];
    float* out = (float*)d_out;

    wt_prep<<<192, 256>>>(Wq, Wk, Wv);

    cudaFuncSetAttribute(proj_kernel,
                         cudaFuncAttributeMaxDynamicSharedMemorySize, PROJ_SMEM);
    proj_kernel<<<BT / 128, 256, PROJ_SMEM>>>(x);

    cudaFuncSetAttribute(attn_kernel,
                         cudaFuncAttributeMaxDynamicSharedMemorySize, ATTN_SMEM_BYTES);
    attn_kernel<<<dim3(T_ / 64, B_), 128, ATTN_SMEM_BYTES>>>(out);
}

// round 14
// speedup vs baseline: 1.2424x; 1.0060x over previous
#include <cuda_runtime.h>
#include <cuda_bf16.h>
#include <cstdint>

#define B_  8
#define T_  2048
#define DM  1024
#define DH  64
#define BT  (B_*T_)

// bf16 hi/lo planes produced by proj, consumed by attn.
// Q, K natural [b*T + t][64]; V transposed [b][d][t]. Q prescaled by 0.125.
__device__ __nv_bfloat16 g_Qh[BT * DH], g_Ql[BT * DH];
__device__ __nv_bfloat16 g_Kh[BT * DH], g_Kl[BT * DH];
__device__ __nv_bfloat16 g_Vth[B_ * DH * T_], g_Vtl[B_ * DH * T_];
// Pre-split, pre-transposed weights: [n][k], n: 0-63 Q, 64-127 K, 128-191 V
__device__ __nv_bfloat16 g_Wt_hi[192 * DM];
__device__ __nv_bfloat16 g_Wt_lo[192 * DM];

// ---------------- mma.sync + misc helpers ----------------
__device__ __forceinline__ void mma_bf16(float* c, const uint32_t* a, const uint32_t* b) {
    asm volatile(
        "mma.sync.aligned.m16n8k16.row.col.f32.bf16.bf16.f32 "
        "{%0,%1,%2,%3}, {%4,%5,%6,%7}, {%8,%9}, {%0,%1,%2,%3};\n"
        : "+f"(c[0]), "+f"(c[1]), "+f"(c[2]), "+f"(c[3])
        : "r"(a[0]), "r"(a[1]), "r"(a[2]), "r"(a[3]), "r"(b[0]), "r"(b[1]));
}
__device__ __forceinline__ uint32_t pack_bf2(__nv_bfloat16 a, __nv_bfloat16 b) {
    __nv_bfloat162 t(a, b);
    return *reinterpret_cast<uint32_t*>(&t);
}
// split pair of fp32 into packed bf16 hi and lo words
__device__ __forceinline__ void split2(float a, float b, uint32_t& hi, uint32_t& lo) {
    __nv_bfloat16 ha = __float2bfloat16(a), hb = __float2bfloat16(b);
    hi = pack_bf2(ha, hb);
    lo = pack_bf2(__float2bfloat16(a - __bfloat162float(ha)),
                  __float2bfloat16(b - __bfloat162float(hb)));
}
__device__ __forceinline__ uint32_t smem_u32(const void* p) {
    uint32_t a;
    asm("{ .reg .u64 t; cvta.to.shared.u64 t, %1; cvt.u32.u64 %0, t; }" : "=r"(a) : "l"(p));
    return a;
}
#define CPA(dst, src)  asm volatile("cp.async.cg.shared.global [%0], [%1], 16;" :: "r"(dst), "l"(src) : "memory")
#define CPA_COMMIT()   asm volatile("cp.async.commit_group;" ::: "memory")
#define CPA_WAIT0()    asm volatile("cp.async.wait_group 0;" ::: "memory")
#define CPA_WAIT1()    asm volatile("cp.async.wait_group 1;" ::: "memory")

// ---------------------------------------------------------------------------
// Kernel 0: split + transpose W -> g_Wt_hi/lo [n][k]
// ---------------------------------------------------------------------------
__global__ void wt_prep(const float* __restrict__ Wq,
                        const float* __restrict__ Wk,
                        const float* __restrict__ Wv)
{
    int n = blockIdx.x;  // 0..191
    const float* W = (n < 64) ? Wq : (n < 128) ? Wk : Wv;
    int nn = n & 63;
    for (int k = threadIdx.x; k < DM; k += blockDim.x) {
        float v = W[(size_t)k * 64 + nn];
        __nv_bfloat16 h = __float2bfloat16(v);
        __nv_bfloat16 l = __float2bfloat16(v - __bfloat162float(h));
        g_Wt_hi[(size_t)n * DM + k] = h;
        g_Wt_lo[(size_t)n * DM + k] = l;
    }
}

// ---------------------------------------------------------------------------
// Kernel 1: QKV projection via mma.sync bf16 hi/lo (validated mainloop).
// Epilogue now writes bf16 hi/lo planes (Q scaled, K natural, V transposed).
// ---------------------------------------------------------------------------
#define PITCH 144
#define SA_HI 0
#define SA_LO (SA_HI + 128 * PITCH)
#define SB_HI (SA_LO + 128 * PITCH)
#define SB_LO (SB_HI + 192 * PITCH)
#define PROJ_SMEM (SB_LO + 192 * PITCH)   // 92160 B

__global__ __launch_bounds__(256) void proj_kernel(const float* __restrict__ x)
{
    extern __shared__ char smem[];
    const int tid  = threadIdx.x;
    const int lane = tid & 31;
    const int wid  = tid >> 5;
    const int mw   = wid >> 1;
    const int nw   = wid & 1;
    const int row0 = blockIdx.x * 128;
    const int lr = lane >> 2;
    const int lc = lane & 3;

    float acc[2][12][4];
    #pragma unroll
    for (int mt = 0; mt < 2; mt++)
        #pragma unroll
        for (int nf = 0; nf < 12; nf++)
            #pragma unroll
            for (int r = 0; r < 4; r++) acc[mt][nf][r] = 0.0f;

    for (int kt = 0; kt < 16; kt++) {
        const int k0 = kt * 64;
        #pragma unroll
        for (int i = 0; i < 8; i++) {
            int lin = tid + i * 256;
            int r = lin >> 4, c4 = (lin & 15) * 4;
            float4 v = *(const float4*)&x[(size_t)(row0 + r) * DM + k0 + c4];
            uint32_t h01, l01, h23, l23;
            split2(v.x, v.y, h01, l01);
            split2(v.z, v.w, h23, l23);
            int off = r * PITCH + c4 * 2;
            *(uint2*)(smem + SA_HI + off) = make_uint2(h01, h23);
            *(uint2*)(smem + SA_LO + off) = make_uint2(l01, l23);
        }
        #pragma unroll
        for (int i = 0; i < 6; i++) {
            int lin = tid + i * 256;
            int n = lin >> 3, c8 = (lin & 7) * 8;
            int off = n * PITCH + c8 * 2;
            *(uint4*)(smem + SB_HI + off) = *(const uint4*)&g_Wt_hi[(size_t)n * DM + k0 + c8];
            *(uint4*)(smem + SB_LO + off) = *(const uint4*)&g_Wt_lo[(size_t)n * DM + k0 + c8];
        }
        __syncthreads();

        #pragma unroll
        for (int ks = 0; ks < 4; ks++) {
            uint32_t ah[2][4], al[2][4];
            #pragma unroll
            for (int mt = 0; mt < 2; mt++) {
                int abase = (mw * 32 + mt * 16 + lr) * PITCH + ks * 32 + lc * 4;
                ah[mt][0] = *(const uint32_t*)(smem + SA_HI + abase);
                ah[mt][1] = *(const uint32_t*)(smem + SA_HI + abase + 8 * PITCH);
                ah[mt][2] = *(const uint32_t*)(smem + SA_HI + abase + 16);
                ah[mt][3] = *(const uint32_t*)(smem + SA_HI + abase + 8 * PITCH + 16);
                al[mt][0] = *(const uint32_t*)(smem + SA_LO + abase);
                al[mt][1] = *(const uint32_t*)(smem + SA_LO + abase + 8 * PITCH);
                al[mt][2] = *(const uint32_t*)(smem + SA_LO + abase + 16);
                al[mt][3] = *(const uint32_t*)(smem + SA_LO + abase + 8 * PITCH + 16);
            }
            #pragma unroll
            for (int nf = 0; nf < 12; nf++) {
                int bbase = (nw * 96 + nf * 8 + lr) * PITCH + ks * 32 + lc * 4;
                uint32_t bh[2], bl[2];
                bh[0] = *(const uint32_t*)(smem + SB_HI + bbase);
                bh[1] = *(const uint32_t*)(smem + SB_HI + bbase + 16);
                bl[0] = *(const uint32_t*)(smem + SB_LO + bbase);
                bl[1] = *(const uint32_t*)(smem + SB_LO + bbase + 16);
                mma_bf16(acc[0][nf], ah[0], bh);
                mma_bf16(acc[1][nf], ah[1], bh);
                mma_bf16(acc[0][nf], al[0], bh);
                mma_bf16(acc[1][nf], al[1], bh);
                mma_bf16(acc[0][nf], ah[0], bl);
                mma_bf16(acc[1][nf], ah[1], bl);
            }
        }
        __syncthreads();
    }

    // --- epilogue: split to bf16 hi/lo planes ---
    #pragma unroll
    for (int mt = 0; mt < 2; mt++) {
        #pragma unroll
        for (int nf = 0; nf < 12; nf++) {
            int c  = nw * 96 + nf * 8 + 2 * lc;
            int r1 = row0 + mw * 32 + mt * 16 + lr;
            int r2 = r1 + 8;
            float v0 = acc[mt][nf][0], v1 = acc[mt][nf][1];
            float v2 = acc[mt][nf][2], v3 = acc[mt][nf][3];
            uint32_t h, l;
            if (c < 64) {
                split2(v0 * 0.125f, v1 * 0.125f, h, l);
                *(uint32_t*)&g_Qh[(size_t)r1 * DH + c] = h;
                *(uint32_t*)&g_Ql[(size_t)r1 * DH + c] = l;
                split2(v2 * 0.125f, v3 * 0.125f, h, l);
                *(uint32_t*)&g_Qh[(size_t)r2 * DH + c] = h;
                *(uint32_t*)&g_Ql[(size_t)r2 * DH + c] = l;
            } else if (c < 128) {
                int cc = c - 64;
                split2(v0, v1, h, l);
                *(uint32_t*)&g_Kh[(size_t)r1 * DH + cc] = h;
                *(uint32_t*)&g_Kl[(size_t)r1 * DH + cc] = l;
                split2(v2, v3, h, l);
                *(uint32_t*)&g_Kh[(size_t)r2 * DH + cc] = h;
                *(uint32_t*)&g_Kl[(size_t)r2 * DH + cc] = l;
            } else {
                int cc = c - 128;
                int b1 = r1 >> 11, t1 = r1 & (T_ - 1);
                int b2 = r2 >> 11, t2 = r2 & (T_ - 1);
                #pragma unroll
                for (int e = 0; e < 2; e++) {
                    float va = e ? v1 : v0, vb = e ? v3 : v2;
                    __nv_bfloat16 ha = __float2bfloat16(va);
                    __nv_bfloat16 hb = __float2bfloat16(vb);
                    size_t i1 = ((size_t)b1 * DH + cc + e) * T_ + t1;
                    size_t i2 = ((size_t)b2 * DH + cc + e) * T_ + t2;
                    g_Vth[i1] = ha;
                    g_Vtl[i1] = __float2bfloat16(va - __bfloat162float(ha));
                    g_Vth[i2] = hb;
                    g_Vtl[i2] = __float2bfloat16(vb - __bfloat162float(hb));
                }
            }
        }
    }
}

// ---------------------------------------------------------------------------
// Kernel 2: causal flash attention via mma.sync bf16 hi/lo.
// Grid (32, 8), 128 threads (4 warps x m16). BQ=BK=64.
// Double-buffered cp.async staging of K (natural) and V^T planes.
// ---------------------------------------------------------------------------
#define PLANE (64 * 144)          // one 64x64 bf16 plane, pitch 144 B
#define ABUF  (4 * PLANE)         // Kh | Kl | Vth | Vtl
#define ATT_SMEM (2 * ABUF)       // 73728 B

__device__ __forceinline__ void stage_tile(uint32_t sdst, int b, int kt, int tid) {
    #pragma unroll
    for (int i = 0; i < 16; i++) {
        const int pl = i >> 2;
        int idx = tid + (i & 3) * 128;     // 0..511
        int r = idx >> 3, c8 = idx & 7;
        const __nv_bfloat16* src;
        if (pl == 0)      src = g_Kh  + ((size_t)b * T_ + kt * 64 + r) * DH + c8 * 8;
        else if (pl == 1) src = g_Kl  + ((size_t)b * T_ + kt * 64 + r) * DH + c8 * 8;
        else if (pl == 2) src = g_Vth + ((size_t)b * DH + r) * T_ + kt * 64 + c8 * 8;
        else              src = g_Vtl + ((size_t)b * DH + r) * T_ + kt * 64 + c8 * 8;
        CPA(sdst + pl * PLANE + r * 144 + c8 * 16, src);
    }
}

__global__ __launch_bounds__(128) void attn_kernel(float* __restrict__ out)
{
    extern __shared__ char sm[];
    const uint32_t sb = smem_u32(sm);
    const int tid  = threadIdx.x;
    const int lane = tid & 31;
    const int w    = tid >> 5;            // 0..3: rows w*16..+15
    const int lr   = lane >> 2;           // 0..7
    const int lc   = lane & 3;            // 0..3
    const int qt   = gridDim.x - 1 - blockIdx.x;
    const int b    = blockIdx.y;
    const int q0   = qt * 64;

    // --- Q fragments (loop-invariant), direct from gmem ---
    uint32_t qh[4][4], ql[4][4];
    {
        size_t r0 = (size_t)b * T_ + q0 + w * 16 + lr;
        #pragma unroll
        for (int ks = 0; ks < 4; ks++) {
            int c = ks * 16 + 2 * lc;
            qh[ks][0] = *(const uint32_t*)&g_Qh[r0 * DH + c];
            qh[ks][1] = *(const uint32_t*)&g_Qh[(r0 + 8) * DH + c];
            qh[ks][2] = *(const uint32_t*)&g_Qh[r0 * DH + c + 8];
            qh[ks][3] = *(const uint32_t*)&g_Qh[(r0 + 8) * DH + c + 8];
            ql[ks][0] = *(const uint32_t*)&g_Ql[r0 * DH + c];
            ql[ks][1] = *(const uint32_t*)&g_Ql[(r0 + 8) * DH + c];
            ql[ks][2] = *(const uint32_t*)&g_Ql[r0 * DH + c + 8];
            ql[ks][3] = *(const uint32_t*)&g_Ql[(r0 + 8) * DH + c + 8];
        }
    }

    stage_tile(sb, b, 0, tid);
    CPA_COMMIT();

    float O[8][4];
    #pragma unroll
    for (int nf = 0; nf < 8; nf++)
        #pragma unroll
        for (int r = 0; r < 4; r++) O[nf][r] = 0.0f;
    float m0 = -1e30f, m1 = -1e30f, l0 = 0.0f, l1 = 0.0f;

    for (int kt = 0; kt <= qt; kt++) {
        const uint32_t cb = sb + (kt & 1) * ABUF;
        if (kt < qt) {
            stage_tile(sb + ((kt + 1) & 1) * ABUF, b, kt + 1, tid);
            CPA_COMMIT();
            CPA_WAIT1();
        } else {
            CPA_WAIT0();
        }
        __syncthreads();

        // --- S = Q K^T (hi/lo 3-MMA) ---
        float S[8][4];
        #pragma unroll
        for (int nf = 0; nf < 8; nf++)
            #pragma unroll
            for (int r = 0; r < 4; r++) S[nf][r] = 0.0f;

        #pragma unroll
        for (int ks = 0; ks < 4; ks++) {
            #pragma unroll
            for (int nf = 0; nf < 8; nf++) {
                uint32_t off = cb + (8 * nf + lr) * 144 + (16 * ks + 2 * lc) * 2;
                uint32_t bh[2], bl[2];
                asm volatile("ld.shared.b32 %0,[%1];" : "=r"(bh[0]) : "r"(off));
                asm volatile("ld.shared.b32 %0,[%1];" : "=r"(bh[1]) : "r"(off + 16));
                asm volatile("ld.shared.b32 %0,[%1];" : "=r"(bl[0]) : "r"(off + PLANE));
                asm volatile("ld.shared.b32 %0,[%1];" : "=r"(bl[1]) : "r"(off + PLANE + 16));
                mma_bf16(S[nf], qh[ks], bh);
                mma_bf16(S[nf], ql[ks], bh);
                mma_bf16(S[nf], qh[ks], bl);
            }
        }

        // --- causal mask on diagonal tile (local coords, q0 cancels) ---
        if (kt == qt) {
            int row = w * 16 + lr;
            #pragma unroll
            for (int nf = 0; nf < 8; nf++) {
                int col = 8 * nf + 2 * lc;
                if (col     > row)     S[nf][0] = -1e30f;
                if (col + 1 > row)     S[nf][1] = -1e30f;
                if (col     > row + 8) S[nf][2] = -1e30f;
                if (col + 1 > row + 8) S[nf][3] = -1e30f;
            }
        }

        // --- online softmax on fragments ---
        float mx0 = -1e30f, mx1 = -1e30f;
        #pragma unroll
        for (int nf = 0; nf < 8; nf++) {
            mx0 = fmaxf(mx0, fmaxf(S[nf][0], S[nf][1]));
            mx1 = fmaxf(mx1, fmaxf(S[nf][2], S[nf][3]));
        }
        mx0 = fmaxf(mx0, __shfl_xor_sync(0xffffffffu, mx0, 1));
        mx0 = fmaxf(mx0, __shfl_xor_sync(0xffffffffu, mx0, 2));
        mx1 = fmaxf(mx1, __shfl_xor_sync(0xffffffffu, mx1, 1));
        mx1 = fmaxf(mx1, __shfl_xor_sync(0xffffffffu, mx1, 2));

        float nm0 = fmaxf(m0, mx0), nm1 = fmaxf(m1, mx1);
        float f0 = __expf(m0 - nm0), f1 = __expf(m1 - nm1);
        m0 = nm0; m1 = nm1;

        float rs0 = 0.0f, rs1 = 0.0f;
        #pragma unroll
        for (int nf = 0; nf < 8; nf++) {
            S[nf][0] = __expf(S[nf][0] - nm0);
            S[nf][1] = __expf(S[nf][1] - nm0);
            S[nf][2] = __expf(S[nf][2] - nm1);
            S[nf][3] = __expf(S[nf][3] - nm1);
            rs0 += S[nf][0] + S[nf][1];
            rs1 += S[nf][2] + S[nf][3];
        }
        rs0 += __shfl_xor_sync(0xffffffffu, rs0, 1);
        rs0 += __shfl_xor_sync(0xffffffffu, rs0, 2);
        rs1 += __shfl_xor_sync(0xffffffffu, rs1, 1);
        rs1 += __shfl_xor_sync(0xffffffffu, rs1, 2);
        l0 = l0 * f0 + rs0;
        l1 = l1 * f1 + rs1;
        #pragma unroll
        for (int nf = 0; nf < 8; nf++) {
            O[nf][0] *= f0; O[nf][1] *= f0;
            O[nf][2] *= f1; O[nf][3] *= f1;
        }

        // --- O += P V (hi/lo 3-MMA); P frags built in-register from S ---
        #pragma unroll
        for (int j = 0; j < 4; j++) {
            uint32_t ah[4], al[4];
            split2(S[2*j][0],   S[2*j][1],   ah[0], al[0]);
            split2(S[2*j][2],   S[2*j][3],   ah[1], al[1]);
            split2(S[2*j+1][0], S[2*j+1][1], ah[2], al[2]);
            split2(S[2*j+1][2], S[2*j+1][3], ah[3], al[3]);
            #pragma unroll
            for (int nf = 0; nf < 8; nf++) {
                uint32_t off = cb + 2 * PLANE + (8 * nf + lr) * 144 + (16 * j + 2 * lc) * 2;
                uint32_t vh[2], vl[2];
                asm volatile("ld.shared.b32 %0,[%1];" : "=r"(vh[0]) : "r"(off));
                asm volatile("ld.shared.b32 %0,[%1];" : "=r"(vh[1]) : "r"(off + 16));
                asm volatile("ld.shared.b32 %0,[%1];" : "=r"(vl[0]) : "r"(off + PLANE));
                asm volatile("ld.shared.b32 %0,[%1];" : "=r"(vl[1]) : "r"(off + PLANE + 16));
                mma_bf16(O[nf], ah, vh);
                mma_bf16(O[nf], al, vh);
                mma_bf16(O[nf], ah, vl);
            }
        }
        __syncthreads();   // all reads of this buffer done before restaging
    }

    // --- epilogue ---
    float inv0 = 1.0f / l0, inv1 = 1.0f / l1;
    size_t r0 = (size_t)b * T_ + q0 + w * 16 + lr;
    size_t r1 = r0 + 8;
    #pragma unroll
    for (int nf = 0; nf < 8; nf++) {
        int col = 8 * nf + 2 * lc;
        *(float2*)&out[r0 * DH + col] = make_float2(O[nf][0] * inv0, O[nf][1] * inv0);
        *(float2*)&out[r1 * DH + col] = make_float2(O[nf][2] * inv1, O[nf][3] * inv1);
    }
}

// ---------------------------------------------------------------------------
extern "C" void kernel_launch(void* const* d_in, const int* in_sizes, int n_in,
                              void* d_out, int out_size)
{
    const float* x  = (const float*)d_in[0];
    const float* Wq = (const float*)d_in[1];
    const float* Wk = (const float*)d_in[2];
    const float* Wv = (const float*)d_in[3];
    float* out = (float*)d_out;

    wt_prep<<<192, 256>>>(Wq, Wk, Wv);

    cudaFuncSetAttribute(proj_kernel,
                         cudaFuncAttributeMaxDynamicSharedMemorySize, PROJ_SMEM);
    proj_kernel<<<BT / 128, 256, PROJ_SMEM>>>(x);

    cudaFuncSetAttribute(attn_kernel,
                         cudaFuncAttributeMaxDynamicSharedMemorySize, ATT_SMEM);
    attn_kernel<<<dim3(T_ / 64, B_), 128, ATT_SMEM>>>(out);
}

// round 16
// speedup vs baseline: 1.8888x; 1.5203x over previous
#include <cuda_runtime.h>
#include <cuda_bf16.h>
#include <cstdint>

#define B_  8
#define T_  2048
#define DM  1024
#define DH  64
#define BT  (B_*T_)

// bf16 hi/lo planes produced by proj, consumed by attn.
// Q, K natural [b*T + t][64]; V transposed [b][d][t]. Q prescaled by 0.125.
__device__ __nv_bfloat16 g_Qh[BT * DH], g_Ql[BT * DH];
__device__ __nv_bfloat16 g_Kh[BT * DH], g_Kl[BT * DH];
__device__ __nv_bfloat16 g_Vth[B_ * DH * T_], g_Vtl[B_ * DH * T_];
// Pre-split, pre-transposed weights: [n][k], n: 0-63 Q, 64-127 K, 128-191 V
__device__ __nv_bfloat16 g_Wt_hi[192 * DM];
__device__ __nv_bfloat16 g_Wt_lo[192 * DM];

// ---------------- mma.sync + misc helpers ----------------
__device__ __forceinline__ void mma_bf16(float* c, const uint32_t* a, const uint32_t* b) {
    asm volatile(
        "mma.sync.aligned.m16n8k16.row.col.f32.bf16.bf16.f32 "
        "{%0,%1,%2,%3}, {%4,%5,%6,%7}, {%8,%9}, {%0,%1,%2,%3};\n"
        : "+f"(c[0]), "+f"(c[1]), "+f"(c[2]), "+f"(c[3])
        : "r"(a[0]), "r"(a[1]), "r"(a[2]), "r"(a[3]), "r"(b[0]), "r"(b[1]));
}
__device__ __forceinline__ uint32_t pack_bf2(__nv_bfloat16 a, __nv_bfloat16 b) {
    __nv_bfloat162 t(a, b);
    return *reinterpret_cast<uint32_t*>(&t);
}
__device__ __forceinline__ void split2(float a, float b, uint32_t& hi, uint32_t& lo) {
    __nv_bfloat16 ha = __float2bfloat16(a), hb = __float2bfloat16(b);
    hi = pack_bf2(ha, hb);
    lo = pack_bf2(__float2bfloat16(a - __bfloat162float(ha)),
                  __float2bfloat16(b - __bfloat162float(hb)));
}
__device__ __forceinline__ uint32_t smem_u32(const void* p) {
    uint32_t a;
    asm("{ .reg .u64 t; cvta.to.shared.u64 t, %1; cvt.u32.u64 %0, t; }" : "=r"(a) : "l"(p));
    return a;
}
#define LDS32(r, off) asm volatile("ld.shared.b32 %0,[%1];" : "=r"(r) : "r"(off))
#define CPA(dst, src)  asm volatile("cp.async.cg.shared.global [%0], [%1], 16;" :: "r"(dst), "l"(src) : "memory")
#define CPA_COMMIT()   asm volatile("cp.async.commit_group;" ::: "memory")
#define CPA_WAIT0()    asm volatile("cp.async.wait_group 0;" ::: "memory")
#define CPA_WAIT1()    asm volatile("cp.async.wait_group 1;" ::: "memory")

// ---------------------------------------------------------------------------
// Kernel 0: split + transpose W -> g_Wt_hi/lo [n][k]
// ---------------------------------------------------------------------------
__global__ void wt_prep(const float* __restrict__ Wq,
                        const float* __restrict__ Wk,
                        const float* __restrict__ Wv)
{
    int n = blockIdx.x;  // 0..191
    const float* W = (n < 64) ? Wq : (n < 128) ? Wk : Wv;
    int nn = n & 63;
    for (int k = threadIdx.x; k < DM; k += blockDim.x) {
        float v = W[(size_t)k * 64 + nn];
        __nv_bfloat16 h = __float2bfloat16(v);
        __nv_bfloat16 l = __float2bfloat16(v - __bfloat162float(h));
        g_Wt_hi[(size_t)n * DM + k] = h;
        g_Wt_lo[(size_t)n * DM + k] = l;
    }
}

// ---------------------------------------------------------------------------
// Kernel 1: QKV projection via mma.sync bf16 hi/lo (validated, UNCHANGED).
// ---------------------------------------------------------------------------
#define PITCH 144
#define SA_HI 0
#define SA_LO (SA_HI + 128 * PITCH)
#define SB_HI (SA_LO + 128 * PITCH)
#define SB_LO (SB_HI + 192 * PITCH)
#define PROJ_SMEM (SB_LO + 192 * PITCH)   // 92160 B

__global__ __launch_bounds__(256) void proj_kernel(const float* __restrict__ x)
{
    extern __shared__ char smem[];
    const int tid  = threadIdx.x;
    const int lane = tid & 31;
    const int wid  = tid >> 5;
    const int mw   = wid >> 1;
    const int nw   = wid & 1;
    const int row0 = blockIdx.x * 128;
    const int lr = lane >> 2;
    const int lc = lane & 3;

    float acc[2][12][4];
    #pragma unroll
    for (int mt = 0; mt < 2; mt++)
        #pragma unroll
        for (int nf = 0; nf < 12; nf++)
            #pragma unroll
            for (int r = 0; r < 4; r++) acc[mt][nf][r] = 0.0f;

    for (int kt = 0; kt < 16; kt++) {
        const int k0 = kt * 64;
        #pragma unroll
        for (int i = 0; i < 8; i++) {
            int lin = tid + i * 256;
            int r = lin >> 4, c4 = (lin & 15) * 4;
            float4 v = *(const float4*)&x[(size_t)(row0 + r) * DM + k0 + c4];
            uint32_t h01, l01, h23, l23;
            split2(v.x, v.y, h01, l01);
            split2(v.z, v.w, h23, l23);
            int off = r * PITCH + c4 * 2;
            *(uint2*)(smem + SA_HI + off) = make_uint2(h01, h23);
            *(uint2*)(smem + SA_LO + off) = make_uint2(l01, l23);
        }
        #pragma unroll
        for (int i = 0; i < 6; i++) {
            int lin = tid + i * 256;
            int n = lin >> 3, c8 = (lin & 7) * 8;
            int off = n * PITCH + c8 * 2;
            *(uint4*)(smem + SB_HI + off) = *(const uint4*)&g_Wt_hi[(size_t)n * DM + k0 + c8];
            *(uint4*)(smem + SB_LO + off) = *(const uint4*)&g_Wt_lo[(size_t)n * DM + k0 + c8];
        }
        __syncthreads();

        #pragma unroll
        for (int ks = 0; ks < 4; ks++) {
            uint32_t ah[2][4], al[2][4];
            #pragma unroll
            for (int mt = 0; mt < 2; mt++) {
                int abase = (mw * 32 + mt * 16 + lr) * PITCH + ks * 32 + lc * 4;
                ah[mt][0] = *(const uint32_t*)(smem + SA_HI + abase);
                ah[mt][1] = *(const uint32_t*)(smem + SA_HI + abase + 8 * PITCH);
                ah[mt][2] = *(const uint32_t*)(smem + SA_HI + abase + 16);
                ah[mt][3] = *(const uint32_t*)(smem + SA_HI + abase + 8 * PITCH + 16);
                al[mt][0] = *(const uint32_t*)(smem + SA_LO + abase);
                al[mt][1] = *(const uint32_t*)(smem + SA_LO + abase + 8 * PITCH);
                al[mt][2] = *(const uint32_t*)(smem + SA_LO + abase + 16);
                al[mt][3] = *(const uint32_t*)(smem + SA_LO + abase + 8 * PITCH + 16);
            }
            #pragma unroll
            for (int nf = 0; nf < 12; nf++) {
                int bbase = (nw * 96 + nf * 8 + lr) * PITCH + ks * 32 + lc * 4;
                uint32_t bh[2], bl[2];
                bh[0] = *(const uint32_t*)(smem + SB_HI + bbase);
                bh[1] = *(const uint32_t*)(smem + SB_HI + bbase + 16);
                bl[0] = *(const uint32_t*)(smem + SB_LO + bbase);
                bl[1] = *(const uint32_t*)(smem + SB_LO + bbase + 16);
                mma_bf16(acc[0][nf], ah[0], bh);
                mma_bf16(acc[1][nf], ah[1], bh);
                mma_bf16(acc[0][nf], al[0], bh);
                mma_bf16(acc[1][nf], al[1], bh);
                mma_bf16(acc[0][nf], ah[0], bl);
                mma_bf16(acc[1][nf], ah[1], bl);
            }
        }
        __syncthreads();
    }

    #pragma unroll
    for (int mt = 0; mt < 2; mt++) {
        #pragma unroll
        for (int nf = 0; nf < 12; nf++) {
            int c  = nw * 96 + nf * 8 + 2 * lc;
            int r1 = row0 + mw * 32 + mt * 16 + lr;
            int r2 = r1 + 8;
            float v0 = acc[mt][nf][0], v1 = acc[mt][nf][1];
            float v2 = acc[mt][nf][2], v3 = acc[mt][nf][3];
            uint32_t h, l;
            if (c < 64) {
                split2(v0 * 0.125f, v1 * 0.125f, h, l);
                *(uint32_t*)&g_Qh[(size_t)r1 * DH + c] = h;
                *(uint32_t*)&g_Ql[(size_t)r1 * DH + c] = l;
                split2(v2 * 0.125f, v3 * 0.125f, h, l);
                *(uint32_t*)&g_Qh[(size_t)r2 * DH + c] = h;
                *(uint32_t*)&g_Ql[(size_t)r2 * DH + c] = l;
            } else if (c < 128) {
                int cc = c - 64;
                split2(v0, v1, h, l);
                *(uint32_t*)&g_Kh[(size_t)r1 * DH + cc] = h;
                *(uint32_t*)&g_Kl[(size_t)r1 * DH + cc] = l;
                split2(v2, v3, h, l);
                *(uint32_t*)&g_Kh[(size_t)r2 * DH + cc] = h;
                *(uint32_t*)&g_Kl[(size_t)r2 * DH + cc] = l;
            } else {
                int cc = c - 128;
                int b1 = r1 >> 11, t1 = r1 & (T_ - 1);
                int b2 = r2 >> 11, t2 = r2 & (T_ - 1);
                #pragma unroll
                for (int e = 0; e < 2; e++) {
                    float va = e ? v1 : v0, vb = e ? v3 : v2;
                    __nv_bfloat16 ha = __float2bfloat16(va);
                    __nv_bfloat16 hb = __float2bfloat16(vb);
                    size_t i1 = ((size_t)b1 * DH + cc + e) * T_ + t1;
                    size_t i2 = ((size_t)b2 * DH + cc + e) * T_ + t2;
                    g_Vth[i1] = ha;
                    g_Vtl[i1] = __float2bfloat16(va - __bfloat162float(ha));
                    g_Vth[i2] = hb;
                    g_Vtl[i2] = __float2bfloat16(vb - __bfloat162float(hb));
                }
            }
        }
    }
}

// ---------------------------------------------------------------------------
// Kernel 2: causal flash attention via mma.sync bf16 hi/lo.
// Restructured: dependent-MMA chains broken by nf-batched issue.
// ---------------------------------------------------------------------------
#define PLANE (64 * 144)
#define ABUF  (4 * PLANE)         // Kh | Kl | Vth | Vtl
#define ATT_SMEM (2 * ABUF)       // 73728 B

__device__ __forceinline__ void stage_tile(uint32_t sdst, int b, int kt, int tid) {
    #pragma unroll
    for (int i = 0; i < 16; i++) {
        const int pl = i >> 2;
        int idx = tid + (i & 3) * 128;
        int r = idx >> 3, c8 = idx & 7;
        const __nv_bfloat16* src;
        if (pl == 0)      src = g_Kh  + ((size_t)b * T_ + kt * 64 + r) * DH + c8 * 8;
        else if (pl == 1) src = g_Kl  + ((size_t)b * T_ + kt * 64 + r) * DH + c8 * 8;
        else if (pl == 2) src = g_Vth + ((size_t)b * DH + r) * T_ + kt * 64 + c8 * 8;
        else              src = g_Vtl + ((size_t)b * DH + r) * T_ + kt * 64 + c8 * 8;
        CPA(sdst + pl * PLANE + r * 144 + c8 * 16, src);
    }
}

__global__ __launch_bounds__(128) void attn_kernel(float* __restrict__ out)
{
    extern __shared__ char sm[];
    const uint32_t sb = smem_u32(sm);
    const int tid  = threadIdx.x;
    const int lane = tid & 31;
    const int w    = tid >> 5;
    const int lr   = lane >> 2;
    const int lc   = lane & 3;
    const int qt   = gridDim.x - 1 - blockIdx.x;
    const int b    = blockIdx.y;
    const int q0   = qt * 64;

    // --- Q fragments (loop-invariant) ---
    uint32_t qh[4][4], ql[4][4];
    {
        size_t r0 = (size_t)b * T_ + q0 + w * 16 + lr;
        #pragma unroll
        for (int ks = 0; ks < 4; ks++) {
            int c = ks * 16 + 2 * lc;
            qh[ks][0] = *(const uint32_t*)&g_Qh[r0 * DH + c];
            qh[ks][1] = *(const uint32_t*)&g_Qh[(r0 + 8) * DH + c];
            qh[ks][2] = *(const uint32_t*)&g_Qh[r0 * DH + c + 8];
            qh[ks][3] = *(const uint32_t*)&g_Qh[(r0 + 8) * DH + c + 8];
            ql[ks][0] = *(const uint32_t*)&g_Ql[r0 * DH + c];
            ql[ks][1] = *(const uint32_t*)&g_Ql[(r0 + 8) * DH + c];
            ql[ks][2] = *(const uint32_t*)&g_Ql[r0 * DH + c + 8];
            ql[ks][3] = *(const uint32_t*)&g_Ql[(r0 + 8) * DH + c + 8];
        }
    }

    stage_tile(sb, b, 0, tid);
    CPA_COMMIT();

    float O[8][4];
    #pragma unroll
    for (int nf = 0; nf < 8; nf++)
        #pragma unroll
        for (int r = 0; r < 4; r++) O[nf][r] = 0.0f;
    float m0 = -1e30f, m1 = -1e30f, l0 = 0.0f, l1 = 0.0f;

    for (int kt = 0; kt <= qt; kt++) {
        const uint32_t cb = sb + (kt & 1) * ABUF;
        if (kt < qt) {
            stage_tile(sb + ((kt + 1) & 1) * ABUF, b, kt + 1, tid);
            CPA_COMMIT();
            CPA_WAIT1();
        } else {
            CPA_WAIT0();
        }
        __syncthreads();

        // --- S = Q K^T : nf-batched issue, dep distance 8 ---
        float S[8][4];
        #pragma unroll
        for (int nf = 0; nf < 8; nf++)
            #pragma unroll
            for (int r = 0; r < 4; r++) S[nf][r] = 0.0f;

        #pragma unroll
        for (int ks = 0; ks < 4; ks++) {
            const uint32_t kcol = (16 * ks + 2 * lc) * 2;
            uint32_t bf[8][2];
            #pragma unroll
            for (int nf = 0; nf < 8; nf++) {
                uint32_t off = cb + (8 * nf + lr) * 144 + kcol;
                LDS32(bf[nf][0], off);
                LDS32(bf[nf][1], off + 16);
            }
            #pragma unroll
            for (int nf = 0; nf < 8; nf++) mma_bf16(S[nf], qh[ks], bf[nf]);
            #pragma unroll
            for (int nf = 0; nf < 8; nf++) mma_bf16(S[nf], ql[ks], bf[nf]);
            #pragma unroll
            for (int nf = 0; nf < 8; nf++) {
                uint32_t off = cb + PLANE + (8 * nf + lr) * 144 + kcol;
                LDS32(bf[nf][0], off);
                LDS32(bf[nf][1], off + 16);
            }
            #pragma unroll
            for (int nf = 0; nf < 8; nf++) mma_bf16(S[nf], qh[ks], bf[nf]);
        }

        // --- causal mask on diagonal tile ---
        if (kt == qt) {
            int row = w * 16 + lr;
            #pragma unroll
            for (int nf = 0; nf < 8; nf++) {
                int col = 8 * nf + 2 * lc;
                if (col     > row)     S[nf][0] = -1e30f;
                if (col + 1 > row)     S[nf][1] = -1e30f;
                if (col     > row + 8) S[nf][2] = -1e30f;
                if (col + 1 > row + 8) S[nf][3] = -1e30f;
            }
        }

        // --- online softmax on fragments ---
        float mx0 = -1e30f, mx1 = -1e30f;
        #pragma unroll
        for (int nf = 0; nf < 8; nf++) {
            mx0 = fmaxf(mx0, fmaxf(S[nf][0], S[nf][1]));
            mx1 = fmaxf(mx1, fmaxf(S[nf][2], S[nf][3]));
        }
        mx0 = fmaxf(mx0, __shfl_xor_sync(0xffffffffu, mx0, 1));
        mx0 = fmaxf(mx0, __shfl_xor_sync(0xffffffffu, mx0, 2));
        mx1 = fmaxf(mx1, __shfl_xor_sync(0xffffffffu, mx1, 1));
        mx1 = fmaxf(mx1, __shfl_xor_sync(0xffffffffu, mx1, 2));

        float nm0 = fmaxf(m0, mx0), nm1 = fmaxf(m1, mx1);
        float f0 = __expf(m0 - nm0), f1 = __expf(m1 - nm1);
        m0 = nm0; m1 = nm1;

        float rs0 = 0.0f, rs1 = 0.0f;
        #pragma unroll
        for (int nf = 0; nf < 8; nf++) {
            S[nf][0] = __expf(S[nf][0] - nm0);
            S[nf][1] = __expf(S[nf][1] - nm0);
            S[nf][2] = __expf(S[nf][2] - nm1);
            S[nf][3] = __expf(S[nf][3] - nm1);
            rs0 += S[nf][0] + S[nf][1];
            rs1 += S[nf][2] + S[nf][3];
        }
        rs0 += __shfl_xor_sync(0xffffffffu, rs0, 1);
        rs0 += __shfl_xor_sync(0xffffffffu, rs0, 2);
        rs1 += __shfl_xor_sync(0xffffffffu, rs1, 1);
        rs1 += __shfl_xor_sync(0xffffffffu, rs1, 2);
        l0 = l0 * f0 + rs0;
        l1 = l1 * f1 + rs1;
        #pragma unroll
        for (int nf = 0; nf < 8; nf++) {
            O[nf][0] *= f0; O[nf][1] *= f0;
            O[nf][2] *= f1; O[nf][3] *= f1;
        }

        // --- P fragments (S registers die into ah/al) ---
        uint32_t ah[4][4], al[4][4];
        #pragma unroll
        for (int j = 0; j < 4; j++) {
            split2(S[2*j][0],   S[2*j][1],   ah[j][0], al[j][0]);
            split2(S[2*j][2],   S[2*j][3],   ah[j][1], al[j][1]);
            split2(S[2*j+1][0], S[2*j+1][1], ah[j][2], al[j][2]);
            split2(S[2*j+1][2], S[2*j+1][3], ah[j][3], al[j][3]);
        }

        // --- O += P V : nf-batched issue, dep distance 8 ---
        #pragma unroll
        for (int j = 0; j < 4; j++) {
            const uint32_t vcol = (16 * j + 2 * lc) * 2;
            uint32_t vf[8][2];
            #pragma unroll
            for (int nf = 0; nf < 8; nf++) {
                uint32_t off = cb + 2 * PLANE + (8 * nf + lr) * 144 + vcol;
                LDS32(vf[nf][0], off);
                LDS32(vf[nf][1], off + 16);
            }
            #pragma unroll
            for (int nf = 0; nf < 8; nf++) mma_bf16(O[nf], ah[j], vf[nf]);
            #pragma unroll
            for (int nf = 0; nf < 8; nf++) mma_bf16(O[nf], al[j], vf[nf]);
            #pragma unroll
            for (int nf = 0; nf < 8; nf++) {
                uint32_t off = cb + 3 * PLANE + (8 * nf + lr) * 144 + vcol;
                LDS32(vf[nf][0], off);
                LDS32(vf[nf][1], off + 16);
            }
            #pragma unroll
            for (int nf = 0; nf < 8; nf++) mma_bf16(O[nf], ah[j], vf[nf]);
        }
        __syncthreads();
    }

    // --- epilogue ---
    float inv0 = 1.0f / l0, inv1 = 1.0f / l1;
    size_t r0 = (size_t)b * T_ + q0 + w * 16 + lr;
    size_t r1 = r0 + 8;
    #pragma unroll
    for (int nf = 0; nf < 8; nf++) {
        int col = 8 * nf + 2 * lc;
        *(float2*)&out[r0 * DH + col] = make_float2(O[nf][0] * inv0, O[nf][1] * inv0);
        *(float2*)&out[r1 * DH + col] = make_float2(O[nf][2] * inv1, O[nf][3] * inv1);
    }
}

// ---------------------------------------------------------------------------
extern "C" void kernel_launch(void* const* d_in, const int* in_sizes, int n_in,
                              void* d_out, int out_size)
{
    const float* x  = (const float*)d_in[0];
    const float* Wq = (const float*)d_in[1];
    const float* Wk = (const float*)d_in[2];
    const float* Wv = (const float*)d_in[3];
    float* out = (float*)d_out;

    wt_prep<<<192, 256>>>(Wq, Wk, Wv);

    cudaFuncSetAttribute(proj_kernel,
                         cudaFuncAttributeMaxDynamicSharedMemorySize, PROJ_SMEM);
    proj_kernel<<<BT / 128, 256, PROJ_SMEM>>>(x);

    cudaFuncSetAttribute(attn_kernel,
                         cudaFuncAttributeMaxDynamicSharedMemorySize, ATT_SMEM);
    attn_kernel<<<dim3(T_ / 64, B_), 128, ATT_SMEM>>>(out);
}

// round 17
// speedup vs baseline: 2.0786x; 1.1004x over previous
#include <cuda_runtime.h>
#include <cuda_bf16.h>
#include <cstdint>

#define B_  8
#define T_  2048
#define DM  1024
#define DH  64
#define BT  (B_*T_)

// bf16 hi/lo planes produced by proj, consumed by attn.
// Q, K natural [b*T + t][64]; V transposed [b][d][t]. Q prescaled by 0.125.
__device__ __nv_bfloat16 g_Qh[BT * DH], g_Ql[BT * DH];
__device__ __nv_bfloat16 g_Kh[BT * DH], g_Kl[BT * DH];
__device__ __nv_bfloat16 g_Vth[B_ * DH * T_], g_Vtl[B_ * DH * T_];
// Pre-split, pre-transposed weights: [n][k], n: 0-63 Q, 64-127 K, 128-191 V
__device__ __nv_bfloat16 g_Wt_hi[192 * DM];
__device__ __nv_bfloat16 g_Wt_lo[192 * DM];

// ---------------- mma.sync + misc helpers ----------------
__device__ __forceinline__ void mma_bf16(float* c, const uint32_t* a, const uint32_t* b) {
    asm volatile(
        "mma.sync.aligned.m16n8k16.row.col.f32.bf16.bf16.f32 "
        "{%0,%1,%2,%3}, {%4,%5,%6,%7}, {%8,%9}, {%0,%1,%2,%3};\n"
        : "+f"(c[0]), "+f"(c[1]), "+f"(c[2]), "+f"(c[3])
        : "r"(a[0]), "r"(a[1]), "r"(a[2]), "r"(a[3]), "r"(b[0]), "r"(b[1]));
}
__device__ __forceinline__ uint32_t pack_bf2(__nv_bfloat16 a, __nv_bfloat16 b) {
    __nv_bfloat162 t(a, b);
    return *reinterpret_cast<uint32_t*>(&t);
}
__device__ __forceinline__ void split2(float a, float b, uint32_t& hi, uint32_t& lo) {
    __nv_bfloat16 ha = __float2bfloat16(a), hb = __float2bfloat16(b);
    hi = pack_bf2(ha, hb);
    lo = pack_bf2(__float2bfloat16(a - __bfloat162float(ha)),
                  __float2bfloat16(b - __bfloat162float(hb)));
}
__device__ __forceinline__ uint32_t smem_u32(const void* p) {
    uint32_t a;
    asm("{ .reg .u64 t; cvta.to.shared.u64 t, %1; cvt.u32.u64 %0, t; }" : "=r"(a) : "l"(p));
    return a;
}
#define LDS32(r, off) asm volatile("ld.shared.b32 %0,[%1];" : "=r"(r) : "r"(off))
#define CPA(dst, src)  asm volatile("cp.async.cg.shared.global [%0], [%1], 16;" :: "r"(dst), "l"(src) : "memory")
#define CPA_COMMIT()   asm volatile("cp.async.commit_group;" ::: "memory")
#define CPA_WAIT0()    asm volatile("cp.async.wait_group 0;" ::: "memory")
#define CPA_WAIT1()    asm volatile("cp.async.wait_group 1;" ::: "memory")

// ---------------------------------------------------------------------------
// Kernel 0: split + transpose W -> g_Wt_hi/lo [n][k]
// ---------------------------------------------------------------------------
__global__ void wt_prep(const float* __restrict__ Wq,
                        const float* __restrict__ Wk,
                        const float* __restrict__ Wv)
{
    int n = blockIdx.x;  // 0..191
    const float* W = (n < 64) ? Wq : (n < 128) ? Wk : Wv;
    int nn = n & 63;
    for (int k = threadIdx.x; k < DM; k += blockDim.x) {
        float v = W[(size_t)k * 64 + nn];
        __nv_bfloat16 h = __float2bfloat16(v);
        __nv_bfloat16 l = __float2bfloat16(v - __bfloat162float(h));
        g_Wt_hi[(size_t)n * DM + k] = h;
        g_Wt_lo[(size_t)n * DM + k] = l;
    }
}

// ---------------------------------------------------------------------------
// Kernel 1: QKV projection via mma.sync bf16 hi/lo.
// Mainloop restructured: nf batched in groups of 6, dep distance 12.
// ---------------------------------------------------------------------------
#define PITCH 144
#define SA_HI 0
#define SA_LO (SA_HI + 128 * PITCH)
#define SB_HI (SA_LO + 128 * PITCH)
#define SB_LO (SB_HI + 192 * PITCH)
#define PROJ_SMEM (SB_LO + 192 * PITCH)   // 92160 B

__global__ __launch_bounds__(256) void proj_kernel(const float* __restrict__ x)
{
    extern __shared__ char smem[];
    const uint32_t sbase = smem_u32(smem);
    const int tid  = threadIdx.x;
    const int lane = tid & 31;
    const int wid  = tid >> 5;
    const int mw   = wid >> 1;
    const int nw   = wid & 1;
    const int row0 = blockIdx.x * 128;
    const int lr = lane >> 2;
    const int lc = lane & 3;

    float acc[2][12][4];
    #pragma unroll
    for (int mt = 0; mt < 2; mt++)
        #pragma unroll
        for (int nf = 0; nf < 12; nf++)
            #pragma unroll
            for (int r = 0; r < 4; r++) acc[mt][nf][r] = 0.0f;

    for (int kt = 0; kt < 16; kt++) {
        const int k0 = kt * 64;
        #pragma unroll
        for (int i = 0; i < 8; i++) {
            int lin = tid + i * 256;
            int r = lin >> 4, c4 = (lin & 15) * 4;
            float4 v = *(const float4*)&x[(size_t)(row0 + r) * DM + k0 + c4];
            uint32_t h01, l01, h23, l23;
            split2(v.x, v.y, h01, l01);
            split2(v.z, v.w, h23, l23);
            int off = r * PITCH + c4 * 2;
            *(uint2*)(smem + SA_HI + off) = make_uint2(h01, h23);
            *(uint2*)(smem + SA_LO + off) = make_uint2(l01, l23);
        }
        #pragma unroll
        for (int i = 0; i < 6; i++) {
            int lin = tid + i * 256;
            int n = lin >> 3, c8 = (lin & 7) * 8;
            int off = n * PITCH + c8 * 2;
            *(uint4*)(smem + SB_HI + off) = *(const uint4*)&g_Wt_hi[(size_t)n * DM + k0 + c8];
            *(uint4*)(smem + SB_LO + off) = *(const uint4*)&g_Wt_lo[(size_t)n * DM + k0 + c8];
        }
        __syncthreads();

        #pragma unroll
        for (int ks = 0; ks < 4; ks++) {
            uint32_t ah[2][4], al[2][4];
            #pragma unroll
            for (int mt = 0; mt < 2; mt++) {
                uint32_t abase = sbase + (mw * 32 + mt * 16 + lr) * PITCH + ks * 32 + lc * 4;
                LDS32(ah[mt][0], abase + SA_HI);
                LDS32(ah[mt][1], abase + SA_HI + 8 * PITCH);
                LDS32(ah[mt][2], abase + SA_HI + 16);
                LDS32(ah[mt][3], abase + SA_HI + 8 * PITCH + 16);
                LDS32(al[mt][0], abase + SA_LO);
                LDS32(al[mt][1], abase + SA_LO + 8 * PITCH);
                LDS32(al[mt][2], abase + SA_LO + 16);
                LDS32(al[mt][3], abase + SA_LO + 8 * PITCH + 16);
            }
            // nf in groups of 6: dep distance 12 per accumulator
            #pragma unroll
            for (int g = 0; g < 2; g++) {
                uint32_t bf[6][2];
                #pragma unroll
                for (int j = 0; j < 6; j++) {
                    uint32_t bbase = sbase + (nw * 96 + (g * 6 + j) * 8 + lr) * PITCH + ks * 32 + lc * 4;
                    LDS32(bf[j][0], bbase + SB_HI);
                    LDS32(bf[j][1], bbase + SB_HI + 16);
                }
                #pragma unroll
                for (int j = 0; j < 6; j++) mma_bf16(acc[0][g*6+j], ah[0], bf[j]);
                #pragma unroll
                for (int j = 0; j < 6; j++) mma_bf16(acc[1][g*6+j], ah[1], bf[j]);
                #pragma unroll
                for (int j = 0; j < 6; j++) mma_bf16(acc[0][g*6+j], al[0], bf[j]);
                #pragma unroll
                for (int j = 0; j < 6; j++) mma_bf16(acc[1][g*6+j], al[1], bf[j]);
                #pragma unroll
                for (int j = 0; j < 6; j++) {
                    uint32_t bbase = sbase + (nw * 96 + (g * 6 + j) * 8 + lr) * PITCH + ks * 32 + lc * 4;
                    LDS32(bf[j][0], bbase + SB_LO);
                    LDS32(bf[j][1], bbase + SB_LO + 16);
                }
                #pragma unroll
                for (int j = 0; j < 6; j++) mma_bf16(acc[0][g*6+j], ah[0], bf[j]);
                #pragma unroll
                for (int j = 0; j < 6; j++) mma_bf16(acc[1][g*6+j], ah[1], bf[j]);
            }
        }
        __syncthreads();
    }

    #pragma unroll
    for (int mt = 0; mt < 2; mt++) {
        #pragma unroll
        for (int nf = 0; nf < 12; nf++) {
            int c  = nw * 96 + nf * 8 + 2 * lc;
            int r1 = row0 + mw * 32 + mt * 16 + lr;
            int r2 = r1 + 8;
            float v0 = acc[mt][nf][0], v1 = acc[mt][nf][1];
            float v2 = acc[mt][nf][2], v3 = acc[mt][nf][3];
            uint32_t h, l;
            if (c < 64) {
                split2(v0 * 0.125f, v1 * 0.125f, h, l);
                *(uint32_t*)&g_Qh[(size_t)r1 * DH + c] = h;
                *(uint32_t*)&g_Ql[(size_t)r1 * DH + c] = l;
                split2(v2 * 0.125f, v3 * 0.125f, h, l);
                *(uint32_t*)&g_Qh[(size_t)r2 * DH + c] = h;
                *(uint32_t*)&g_Ql[(size_t)r2 * DH + c] = l;
            } else if (c < 128) {
                int cc = c - 64;
                split2(v0, v1, h, l);
                *(uint32_t*)&g_Kh[(size_t)r1 * DH + cc] = h;
                *(uint32_t*)&g_Kl[(size_t)r1 * DH + cc] = l;
                split2(v2, v3, h, l);
                *(uint32_t*)&g_Kh[(size_t)r2 * DH + cc] = h;
                *(uint32_t*)&g_Kl[(size_t)r2 * DH + cc] = l;
            } else {
                int cc = c - 128;
                int b1 = r1 >> 11, t1 = r1 & (T_ - 1);
                int b2 = r2 >> 11, t2 = r2 & (T_ - 1);
                #pragma unroll
                for (int e = 0; e < 2; e++) {
                    float va = e ? v1 : v0, vb = e ? v3 : v2;
                    __nv_bfloat16 ha = __float2bfloat16(va);
                    __nv_bfloat16 hb = __float2bfloat16(vb);
                    size_t i1 = ((size_t)b1 * DH + cc + e) * T_ + t1;
                    size_t i2 = ((size_t)b2 * DH + cc + e) * T_ + t2;
                    g_Vth[i1] = ha;
                    g_Vtl[i1] = __float2bfloat16(va - __bfloat162float(ha));
                    g_Vth[i2] = hb;
                    g_Vtl[i2] = __float2bfloat16(vb - __bfloat162float(hb));
                }
            }
        }
    }
}

// ---------------------------------------------------------------------------
// Kernel 2: causal flash attention via mma.sync bf16 hi/lo (UNCHANGED from R16).
// ---------------------------------------------------------------------------
#define PLANE (64 * 144)
#define ABUF  (4 * PLANE)         // Kh | Kl | Vth | Vtl
#define ATT_SMEM (2 * ABUF)       // 73728 B

__device__ __forceinline__ void stage_tile(uint32_t sdst, int b, int kt, int tid) {
    #pragma unroll
    for (int i = 0; i < 16; i++) {
        const int pl = i >> 2;
        int idx = tid + (i & 3) * 128;
        int r = idx >> 3, c8 = idx & 7;
        const __nv_bfloat16* src;
        if (pl == 0)      src = g_Kh  + ((size_t)b * T_ + kt * 64 + r) * DH + c8 * 8;
        else if (pl == 1) src = g_Kl  + ((size_t)b * T_ + kt * 64 + r) * DH + c8 * 8;
        else if (pl == 2) src = g_Vth + ((size_t)b * DH + r) * T_ + kt * 64 + c8 * 8;
        else              src = g_Vtl + ((size_t)b * DH + r) * T_ + kt * 64 + c8 * 8;
        CPA(sdst + pl * PLANE + r * 144 + c8 * 16, src);
    }
}

__global__ __launch_bounds__(128) void attn_kernel(float* __restrict__ out)
{
    extern __shared__ char sm[];
    const uint32_t sb = smem_u32(sm);
    const int tid  = threadIdx.x;
    const int lane = tid & 31;
    const int w    = tid >> 5;
    const int lr   = lane >> 2;
    const int lc   = lane & 3;
    const int qt   = gridDim.x - 1 - blockIdx.x;
    const int b    = blockIdx.y;
    const int q0   = qt * 64;

    uint32_t qh[4][4], ql[4][4];
    {
        size_t r0 = (size_t)b * T_ + q0 + w * 16 + lr;
        #pragma unroll
        for (int ks = 0; ks < 4; ks++) {
            int c = ks * 16 + 2 * lc;
            qh[ks][0] = *(const uint32_t*)&g_Qh[r0 * DH + c];
            qh[ks][1] = *(const uint32_t*)&g_Qh[(r0 + 8) * DH + c];
            qh[ks][2] = *(const uint32_t*)&g_Qh[r0 * DH + c + 8];
            qh[ks][3] = *(const uint32_t*)&g_Qh[(r0 + 8) * DH + c + 8];
            ql[ks][0] = *(const uint32_t*)&g_Ql[r0 * DH + c];
            ql[ks][1] = *(const uint32_t*)&g_Ql[(r0 + 8) * DH + c];
            ql[ks][2] = *(const uint32_t*)&g_Ql[r0 * DH + c + 8];
            ql[ks][3] = *(const uint32_t*)&g_Ql[(r0 + 8) * DH + c + 8];
        }
    }

    stage_tile(sb, b, 0, tid);
    CPA_COMMIT();

    float O[8][4];
    #pragma unroll
    for (int nf = 0; nf < 8; nf++)
        #pragma unroll
        for (int r = 0; r < 4; r++) O[nf][r] = 0.0f;
    float m0 = -1e30f, m1 = -1e30f, l0 = 0.0f, l1 = 0.0f;

    for (int kt = 0; kt <= qt; kt++) {
        const uint32_t cb = sb + (kt & 1) * ABUF;
        if (kt < qt) {
            stage_tile(sb + ((kt + 1) & 1) * ABUF, b, kt + 1, tid);
            CPA_COMMIT();
            CPA_WAIT1();
        } else {
            CPA_WAIT0();
        }
        __syncthreads();

        float S[8][4];
        #pragma unroll
        for (int nf = 0; nf < 8; nf++)
            #pragma unroll
            for (int r = 0; r < 4; r++) S[nf][r] = 0.0f;

        #pragma unroll
        for (int ks = 0; ks < 4; ks++) {
            const uint32_t kcol = (16 * ks + 2 * lc) * 2;
            uint32_t bf[8][2];
            #pragma unroll
            for (int nf = 0; nf < 8; nf++) {
                uint32_t off = cb + (8 * nf + lr) * 144 + kcol;
                LDS32(bf[nf][0], off);
                LDS32(bf[nf][1], off + 16);
            }
            #pragma unroll
            for (int nf = 0; nf < 8; nf++) mma_bf16(S[nf], qh[ks], bf[nf]);
            #pragma unroll
            for (int nf = 0; nf < 8; nf++) mma_bf16(S[nf], ql[ks], bf[nf]);
            #pragma unroll
            for (int nf = 0; nf < 8; nf++) {
                uint32_t off = cb + PLANE + (8 * nf + lr) * 144 + kcol;
                LDS32(bf[nf][0], off);
                LDS32(bf[nf][1], off + 16);
            }
            #pragma unroll
            for (int nf = 0; nf < 8; nf++) mma_bf16(S[nf], qh[ks], bf[nf]);
        }

        if (kt == qt) {
            int row = w * 16 + lr;
            #pragma unroll
            for (int nf = 0; nf < 8; nf++) {
                int col = 8 * nf + 2 * lc;
                if (col     > row)     S[nf][0] = -1e30f;
                if (col + 1 > row)     S[nf][1] = -1e30f;
                if (col     > row + 8) S[nf][2] = -1e30f;
                if (col + 1 > row + 8) S[nf][3] = -1e30f;
            }
        }

        float mx0 = -1e30f, mx1 = -1e30f;
        #pragma unroll
        for (int nf = 0; nf < 8; nf++) {
            mx0 = fmaxf(mx0, fmaxf(S[nf][0], S[nf][1]));
            mx1 = fmaxf(mx1, fmaxf(S[nf][2], S[nf][3]));
        }
        mx0 = fmaxf(mx0, __shfl_xor_sync(0xffffffffu, mx0, 1));
        mx0 = fmaxf(mx0, __shfl_xor_sync(0xffffffffu, mx0, 2));
        mx1 = fmaxf(mx1, __shfl_xor_sync(0xffffffffu, mx1, 1));
        mx1 = fmaxf(mx1, __shfl_xor_sync(0xffffffffu, mx1, 2));

        float nm0 = fmaxf(m0, mx0), nm1 = fmaxf(m1, mx1);
        float f0 = __expf(m0 - nm0), f1 = __expf(m1 - nm1);
        m0 = nm0; m1 = nm1;

        float rs0 = 0.0f, rs1 = 0.0f;
        #pragma unroll
        for (int nf = 0; nf < 8; nf++) {
            S[nf][0] = __expf(S[nf][0] - nm0);
            S[nf][1] = __expf(S[nf][1] - nm0);
            S[nf][2] = __expf(S[nf][2] - nm1);
            S[nf][3] = __expf(S[nf][3] - nm1);
            rs0 += S[nf][0] + S[nf][1];
            rs1 += S[nf][2] + S[nf][3];
        }
        rs0 += __shfl_xor_sync(0xffffffffu, rs0, 1);
        rs0 += __shfl_xor_sync(0xffffffffu, rs0, 2);
        rs1 += __shfl_xor_sync(0xffffffffu, rs1, 1);
        rs1 += __shfl_xor_sync(0xffffffffu, rs1, 2);
        l0 = l0 * f0 + rs0;
        l1 = l1 * f1 + rs1;
        #pragma unroll
        for (int nf = 0; nf < 8; nf++) {
            O[nf][0] *= f0; O[nf][1] *= f0;
            O[nf][2] *= f1; O[nf][3] *= f1;
        }

        uint32_t ah[4][4], al[4][4];
        #pragma unroll
        for (int j = 0; j < 4; j++) {
            split2(S[2*j][0],   S[2*j][1],   ah[j][0], al[j][0]);
            split2(S[2*j][2],   S[2*j][3],   ah[j][1], al[j][1]);
            split2(S[2*j+1][0], S[2*j+1][1], ah[j][2], al[j][2]);
            split2(S[2*j+1][2], S[2*j+1][3], ah[j][3], al[j][3]);
        }

        #pragma unroll
        for (int j = 0; j < 4; j++) {
            const uint32_t vcol = (16 * j + 2 * lc) * 2;
            uint32_t vf[8][2];
            #pragma unroll
            for (int nf = 0; nf < 8; nf++) {
                uint32_t off = cb + 2 * PLANE + (8 * nf + lr) * 144 + vcol;
                LDS32(vf[nf][0], off);
                LDS32(vf[nf][1], off + 16);
            }
            #pragma unroll
            for (int nf = 0; nf < 8; nf++) mma_bf16(O[nf], ah[j], vf[nf]);
            #pragma unroll
            for (int nf = 0; nf < 8; nf++) mma_bf16(O[nf], al[j], vf[nf]);
            #pragma unroll
            for (int nf = 0; nf < 8; nf++) {
                uint32_t off = cb + 3 * PLANE + (8 * nf + lr) * 144 + vcol;
                LDS32(vf[nf][0], off);
                LDS32(vf[nf][1], off + 16);
            }
            #pragma unroll
            for (int nf = 0; nf < 8; nf++) mma_bf16(O[nf], ah[j], vf[nf]);
        }
        __syncthreads();
    }

    float inv0 = 1.0f / l0, inv1 = 1.0f / l1;
    size_t r0 = (size_t)b * T_ + q0 + w * 16 + lr;
    size_t r1 = r0 + 8;
    #pragma unroll
    for (int nf = 0; nf < 8; nf++) {
        int col = 8 * nf + 2 * lc;
        *(float2*)&out[r0 * DH + col] = make_float2(O[nf][0] * inv0, O[nf][1] * inv0);
        *(float2*)&out[r1 * DH + col] = make_float2(O[nf][2] * inv1, O[nf][3] * inv1);
    }
}

// ---------------------------------------------------------------------------
extern "C" void kernel_launch(void* const* d_in, const int* in_sizes, int n_in,
                              void* d_out, int out_size)
{
    const float* x  = (const float*)d_in[0];
    const float* Wq = (const float*)d_in[1];
    const float* Wk = (const float*)d_in[2];
    const float* Wv = (const float*)d_in[3];
    float* out = (float*)d_out;

    wt_prep<<<192, 256>>>(Wq, Wk, Wv);

    cudaFuncSetAttribute(proj_kernel,
                         cudaFuncAttributeMaxDynamicSharedMemorySize, PROJ_SMEM);
    proj_kernel<<<BT / 128, 256, PROJ_SMEM>>>(x);

    cudaFuncSetAttribute(attn_kernel,
                         cudaFuncAttributeMaxDynamicSharedMemorySize, ATT_SMEM);
    attn_kernel<<<dim3(T_ / 64, B_), 128, ATT_SMEM>>>(out);
}